// round 1
// baseline (speedup 1.0000x reference)
#include <cuda_runtime.h>
#include <math.h>

#define L_SEQ 2048
#define E_DIM 2048
#define H_NUM 16
#define D_HEAD 128
#define E3 6144

// Scratch (device globals: allocation-free rule)
__device__ float g_qkv[L_SEQ * E3];    // [L, 3E]
__device__ float g_ctx[L_SEQ * E_DIM]; // [L, E]

// ---------------------------------------------------------------------------
// C[M,N] = A[M,K] @ B[N,K]^T + bias[N]   (torch Linear convention)
// 128x128 block, BK=16, 8x8 micro-tile, register prefetch double buffer.
// ---------------------------------------------------------------------------
__global__ __launch_bounds__(256) void gemm_nt_bias(
    const float* __restrict__ A, const float* __restrict__ B,
    const float* __restrict__ bias, float* __restrict__ C,
    int M, int N, int K)
{
    __shared__ float As[16][132];
    __shared__ float Bs[16][132];

    const int tid = threadIdx.x;
    const int tx  = tid & 15;
    const int ty  = tid >> 4;
    const int lr  = tid >> 2;          // 0..63
    const int lc  = (tid & 3) * 4;     // 0,4,8,12

    const float* Ap = A + (size_t)(blockIdx.y * 128) * K;
    const float* Bp = B + (size_t)(blockIdx.x * 128) * K;

    float acc[8][8];
#pragma unroll
    for (int i = 0; i < 8; i++)
#pragma unroll
        for (int j = 0; j < 8; j++) acc[i][j] = 0.f;

    float4 ar[2], br[2];
#pragma unroll
    for (int i = 0; i < 2; i++) {
        ar[i] = *(const float4*)(Ap + (size_t)(lr + 64 * i) * K + lc);
        br[i] = *(const float4*)(Bp + (size_t)(lr + 64 * i) * K + lc);
    }

    for (int k0 = 0; k0 < K; k0 += 16) {
#pragma unroll
        for (int i = 0; i < 2; i++) {
            int r = lr + 64 * i;
            As[lc + 0][r] = ar[i].x; As[lc + 1][r] = ar[i].y;
            As[lc + 2][r] = ar[i].z; As[lc + 3][r] = ar[i].w;
            Bs[lc + 0][r] = br[i].x; Bs[lc + 1][r] = br[i].y;
            Bs[lc + 2][r] = br[i].z; Bs[lc + 3][r] = br[i].w;
        }
        __syncthreads();

        if (k0 + 16 < K) {
#pragma unroll
            for (int i = 0; i < 2; i++) {
                ar[i] = *(const float4*)(Ap + (size_t)(lr + 64 * i) * K + (k0 + 16) + lc);
                br[i] = *(const float4*)(Bp + (size_t)(lr + 64 * i) * K + (k0 + 16) + lc);
            }
        }

#pragma unroll
        for (int kk = 0; kk < 16; kk++) {
            float4 a0 = *(const float4*)&As[kk][ty * 8];
            float4 a1 = *(const float4*)&As[kk][ty * 8 + 4];
            float4 b0 = *(const float4*)&Bs[kk][tx * 8];
            float4 b1 = *(const float4*)&Bs[kk][tx * 8 + 4];
            float a[8] = {a0.x, a0.y, a0.z, a0.w, a1.x, a1.y, a1.z, a1.w};
            float b[8] = {b0.x, b0.y, b0.z, b0.w, b1.x, b1.y, b1.z, b1.w};
#pragma unroll
            for (int i = 0; i < 8; i++)
#pragma unroll
                for (int j = 0; j < 8; j++)
                    acc[i][j] = fmaf(a[i], b[j], acc[i][j]);
        }
        __syncthreads();
    }

    const int cx = blockIdx.x * 128 + tx * 8;
    float bv[8];
#pragma unroll
    for (int j = 0; j < 8; j++) bv[j] = bias[cx + j];
#pragma unroll
    for (int i = 0; i < 8; i++) {
        int row = blockIdx.y * 128 + ty * 8 + i;
        float4 o0 = make_float4(acc[i][0] + bv[0], acc[i][1] + bv[1],
                                acc[i][2] + bv[2], acc[i][3] + bv[3]);
        float4 o1 = make_float4(acc[i][4] + bv[4], acc[i][5] + bv[5],
                                acc[i][6] + bv[6], acc[i][7] + bv[7]);
        *(float4*)(C + (size_t)row * N + cx)     = o0;
        *(float4*)(C + (size_t)row * N + cx + 4) = o1;
    }
}

// ---------------------------------------------------------------------------
// Fused attention, flash style: per (q-block of 128, head) CTA.
// S = scale*Q@K^T + bias ; online softmax ; ctx += P@V (registers).
// ---------------------------------------------------------------------------
#define AT_BQ 128
#define AT_BK 64
#define KS_STRIDE 132
#define SS_STRIDE 68
#define ATT_SMEM_FLOATS (128*128 + 64*KS_STRIDE + 64*128 + 128*SS_STRIDE + 3*128)
#define ATT_SMEM_BYTES (ATT_SMEM_FLOATS * 4)

__global__ __launch_bounds__(256, 1) void attn_kernel(
    const float* __restrict__ qkv, const float* __restrict__ biasM,
    float* __restrict__ ctxOut)
{
    extern __shared__ float sm[];
    float* Qs   = sm;                       // [128][128]
    float* Ks   = Qs + 128 * 128;           // [64][132]
    float* Vs   = Ks + 64 * KS_STRIDE;      // [64][128]
    float* Ss   = Vs + 64 * 128;            // [128][68]
    float* sm_m = Ss + 128 * SS_STRIDE;     // [128]
    float* sm_l = sm_m + 128;               // [128]
    float* sm_a = sm_l + 128;               // [128]

    const int tid = threadIdx.x;
    const int tx = tid & 15, ty = tid >> 4;
    const int h  = blockIdx.y;
    const int q0 = blockIdx.x * AT_BQ;

    // Load Q tile [128][128]
    {
        const float* qbase = qkv + (size_t)q0 * E3 + h * D_HEAD;
#pragma unroll
        for (int i = 0; i < 16; i++) {
            int f = tid + i * 256;       // 0..4095 float4 ids
            int r = f >> 5;              // 0..127
            int c = (f & 31) * 4;
            *(float4*)&Qs[r * 128 + c] = *(const float4*)(qbase + (size_t)r * E3 + c);
        }
    }
    if (tid < 128) { sm_m[tid] = -INFINITY; sm_l[tid] = 0.f; }

    float ctx[8][8];
#pragma unroll
    for (int i = 0; i < 8; i++)
#pragma unroll
        for (int j = 0; j < 8; j++) ctx[i][j] = 0.f;

    const float scale = 0.088388347648318447f; // 1/sqrt(128)

    for (int kt = 0; kt < L_SEQ / AT_BK; kt++) {
        const int k0 = kt * AT_BK;
        __syncthreads();   // prev iter consumers done; Q/stat init done (iter 0)

        // Load K, V tiles [64][128]
        {
            const float* kbase = qkv + (size_t)k0 * E3 + E_DIM     + h * D_HEAD;
            const float* vbase = qkv + (size_t)k0 * E3 + 2 * E_DIM + h * D_HEAD;
#pragma unroll
            for (int i = 0; i < 8; i++) {
                int f = tid + i * 256;   // 0..2047
                int r = f >> 5;          // 0..63
                int c = (f & 31) * 4;
                *(float4*)&Ks[r * KS_STRIDE + c] = *(const float4*)(kbase + (size_t)r * E3 + c);
                *(float4*)&Vs[r * 128 + c]       = *(const float4*)(vbase + (size_t)r * E3 + c);
            }
        }
        __syncthreads();

        // S tile: rows ty*8+i (8), cols tx+16*j (4, strided for bank spread)
        float sacc[8][4];
#pragma unroll
        for (int i = 0; i < 8; i++)
#pragma unroll
            for (int j = 0; j < 4; j++) sacc[i][j] = 0.f;

#pragma unroll 2
        for (int d4 = 0; d4 < 32; d4++) {
            float4 q[8];
#pragma unroll
            for (int i = 0; i < 8; i++)
                q[i] = *(const float4*)&Qs[(ty * 8 + i) * 128 + d4 * 4];
#pragma unroll
            for (int dd = 0; dd < 4; dd++) {
                float kv[4];
#pragma unroll
                for (int j = 0; j < 4; j++)
                    kv[j] = Ks[(tx + 16 * j) * KS_STRIDE + d4 * 4 + dd];
#pragma unroll
                for (int i = 0; i < 8; i++) {
                    float qv = (dd == 0) ? q[i].x : (dd == 1) ? q[i].y
                             : (dd == 2) ? q[i].z : q[i].w;
#pragma unroll
                    for (int j = 0; j < 4; j++)
                        sacc[i][j] = fmaf(qv, kv[j], sacc[i][j]);
                }
            }
        }

        // scale + bias, write to Ss
#pragma unroll
        for (int i = 0; i < 8; i++) {
            int qr = ty * 8 + i;
            const float* brow = biasM + (size_t)(q0 + qr) * L_SEQ + k0;
#pragma unroll
            for (int j = 0; j < 4; j++) {
                int kc = tx + 16 * j;
                Ss[qr * SS_STRIDE + kc] = fmaf(sacc[i][j], scale, brow[kc]);
            }
        }
        __syncthreads();

        // Online softmax row update: 2 threads per row
        {
            int row = tid >> 1, half = tid & 1;
            float* srow = &Ss[row * SS_STRIDE + half * 32];
            float mloc = -INFINITY;
#pragma unroll
            for (int c = 0; c < 32; c++) mloc = fmaxf(mloc, srow[c]);
            mloc = fmaxf(mloc, __shfl_xor_sync(0xffffffffu, mloc, 1));
            float mold = sm_m[row];
            float mnew = fmaxf(mold, mloc);
            float ssum = 0.f;
#pragma unroll
            for (int c = 0; c < 32; c++) {
                float p = __expf(srow[c] - mnew);
                srow[c] = p;
                ssum += p;
            }
            ssum += __shfl_xor_sync(0xffffffffu, ssum, 1);
            if (half == 0) {
                float alpha = __expf(mold - mnew);
                sm_m[row] = mnew;
                sm_a[row] = alpha;
                sm_l[row] = sm_l[row] * alpha + ssum;
            }
        }
        __syncthreads();

        // ctx = ctx*alpha + P @ V
        float al[8];
#pragma unroll
        for (int i = 0; i < 8; i++) al[i] = sm_a[ty * 8 + i];
#pragma unroll
        for (int i = 0; i < 8; i++)
#pragma unroll
            for (int j = 0; j < 8; j++) ctx[i][j] *= al[i];

#pragma unroll 4
        for (int kk = 0; kk < AT_BK; kk++) {
            float p[8];
#pragma unroll
            for (int i = 0; i < 8; i++) p[i] = Ss[(ty * 8 + i) * SS_STRIDE + kk];
            float4 v0 = *(const float4*)&Vs[kk * 128 + tx * 8];
            float4 v1 = *(const float4*)&Vs[kk * 128 + tx * 8 + 4];
            float v[8] = {v0.x, v0.y, v0.z, v0.w, v1.x, v1.y, v1.z, v1.w};
#pragma unroll
            for (int i = 0; i < 8; i++)
#pragma unroll
                for (int j = 0; j < 8; j++)
                    ctx[i][j] = fmaf(p[i], v[j], ctx[i][j]);
        }
    }

    // Normalize + write ctx [L, E] (head-interleaved columns)
#pragma unroll
    for (int i = 0; i < 8; i++) {
        int qr = ty * 8 + i;
        float inv = 1.0f / sm_l[qr];
        float4 o0 = make_float4(ctx[i][0] * inv, ctx[i][1] * inv,
                                ctx[i][2] * inv, ctx[i][3] * inv);
        float4 o1 = make_float4(ctx[i][4] * inv, ctx[i][5] * inv,
                                ctx[i][6] * inv, ctx[i][7] * inv);
        float* dst = ctxOut + (size_t)(q0 + qr) * E_DIM + h * D_HEAD + tx * 8;
        *(float4*)dst       = o0;
        *(float4*)(dst + 4) = o1;
    }
}

// ---------------------------------------------------------------------------
extern "C" void kernel_launch(void* const* d_in, const int* in_sizes, int n_in,
                              void* d_out, int out_size)
{
    const float* x     = (const float*)d_in[0];
    const float* biasM = (const float*)d_in[1];
    const float* w_in  = (const float*)d_in[2];
    const float* b_in  = (const float*)d_in[3];
    const float* w_out = (const float*)d_in[4];
    const float* b_out = (const float*)d_in[5];
    float* out = (float*)d_out;

    float *qkv_p, *ctx_p;
    cudaGetSymbolAddress((void**)&qkv_p, g_qkv);
    cudaGetSymbolAddress((void**)&ctx_p, g_ctx);

    cudaFuncSetAttribute(attn_kernel, cudaFuncAttributeMaxDynamicSharedMemorySize,
                         ATT_SMEM_BYTES);

    // 1) QKV = x @ W_in^T + b_in   [2048, 6144]
    gemm_nt_bias<<<dim3(E3 / 128, L_SEQ / 128), 256>>>(
        x, w_in, b_in, qkv_p, L_SEQ, E3, E_DIM);

    // 2) Fused attention -> ctx [2048, 2048]
    attn_kernel<<<dim3(L_SEQ / AT_BQ, H_NUM), 256, ATT_SMEM_BYTES>>>(
        qkv_p, biasM, ctx_p);

    // 3) out = ctx @ W_out^T + b_out   [2048, 2048]
    gemm_nt_bias<<<dim3(E_DIM / 128, L_SEQ / 128), 256>>>(
        ctx_p, w_out, b_out, out, L_SEQ, E_DIM, E_DIM);
}

// round 3
// speedup vs baseline: 1.6472x; 1.6472x over previous
#include <cuda_runtime.h>
#include <cuda_bf16.h>
#include <cstdint>
#include <math.h>

#define L_SEQ 2048
#define E_DIM 2048
#define H_NUM 16
#define D_HEAD 128
#define E3 6144

// ---------------------------------------------------------------------------
// Device-global scratch (allocation-free rule)
// ---------------------------------------------------------------------------
__device__ __align__(16) float g_qkv[L_SEQ * E3];    // [L, 3E] fp32
__device__ __align__(16) float g_ctx[L_SEQ * E_DIM]; // [L, E]  fp32
__device__ __align__(16) __nv_bfloat16 g_xh[L_SEQ * E_DIM];
__device__ __align__(16) __nv_bfloat16 g_xl[L_SEQ * E_DIM];
__device__ __align__(16) __nv_bfloat16 g_wih[E3 * E_DIM];
__device__ __align__(16) __nv_bfloat16 g_wil[E3 * E_DIM];
__device__ __align__(16) __nv_bfloat16 g_woh[E_DIM * E_DIM];
__device__ __align__(16) __nv_bfloat16 g_wol[E_DIM * E_DIM];
__device__ __align__(16) __nv_bfloat16 g_ch[L_SEQ * E_DIM];
__device__ __align__(16) __nv_bfloat16 g_cl[L_SEQ * E_DIM];

__device__ __forceinline__ uint32_t smem_u32(const void* p) {
    uint32_t a;
    asm("{ .reg .u64 t; cvta.to.shared.u64 t, %1; cvt.u32.u64 %0, t; }" : "=r"(a) : "l"(p));
    return a;
}

// ---------------------------------------------------------------------------
// fp32 -> split bf16 (hi + lo)
// ---------------------------------------------------------------------------
__global__ void split_bf16_kernel(const float* __restrict__ in,
                                  __nv_bfloat16* __restrict__ hi,
                                  __nv_bfloat16* __restrict__ lo, int n4)
{
    int i = blockIdx.x * blockDim.x + threadIdx.x;
    if (i >= n4) return;
    float4 v = ((const float4*)in)[i];
    __nv_bfloat16 hx = __float2bfloat16(v.x);
    __nv_bfloat16 hy = __float2bfloat16(v.y);
    __nv_bfloat16 hz = __float2bfloat16(v.z);
    __nv_bfloat16 hw = __float2bfloat16(v.w);
    __nv_bfloat16 lx = __float2bfloat16(v.x - __bfloat162float(hx));
    __nv_bfloat16 ly = __float2bfloat16(v.y - __bfloat162float(hy));
    __nv_bfloat16 lz = __float2bfloat16(v.z - __bfloat162float(hz));
    __nv_bfloat16 lw = __float2bfloat16(v.w - __bfloat162float(hw));
    ((__nv_bfloat162*)hi)[2 * i]     = __nv_bfloat162(hx, hy);
    ((__nv_bfloat162*)hi)[2 * i + 1] = __nv_bfloat162(hz, hw);
    ((__nv_bfloat162*)lo)[2 * i]     = __nv_bfloat162(lx, ly);
    ((__nv_bfloat162*)lo)[2 * i + 1] = __nv_bfloat162(lz, lw);
}

// ---------------------------------------------------------------------------
// Split-bf16 mma.sync GEMM: C[M,N] = A[M,K] @ B[N,K]^T + bias[N]
// CTA 128x128, 8 warps (2x4), warp tile 64x32, K-chunk 32, cp.async 2-stage.
// 3 passes: AhBh + AlBh + AhBl into shared fp32 accumulators.
// ---------------------------------------------------------------------------
#define GM_TILE_BYTES 8192                 // 128 rows x 64 B
#define GM_STAGE (4 * GM_TILE_BYTES)       // Ah, Al, Bh, Bl
#define GM_SMEM (2 * GM_STAGE)             // 65536

__device__ __forceinline__ void cp_async16(uint32_t dst, const void* src) {
    asm volatile("cp.async.cg.shared.global [%0], [%1], 16;" :: "r"(dst), "l"(src));
}
__device__ __forceinline__ void cp_commit() {
    asm volatile("cp.async.commit_group;" ::: "memory");
}
__device__ __forceinline__ void cp_wait1() {
    asm volatile("cp.async.wait_group 1;" ::: "memory");
}
__device__ __forceinline__ void ldm_x4(uint32_t* r, uint32_t addr) {
    asm volatile("ldmatrix.sync.aligned.m8n8.x4.shared.b16 {%0,%1,%2,%3}, [%4];"
                 : "=r"(r[0]), "=r"(r[1]), "=r"(r[2]), "=r"(r[3]) : "r"(addr));
}
__device__ __forceinline__ void mma_bf16(float* c, const uint32_t* a, const uint32_t* b) {
    asm volatile(
        "mma.sync.aligned.m16n8k16.row.col.f32.bf16.bf16.f32 "
        "{%0,%1,%2,%3}, {%4,%5,%6,%7}, {%8,%9}, {%0,%1,%2,%3};"
        : "+f"(c[0]), "+f"(c[1]), "+f"(c[2]), "+f"(c[3])
        : "r"(a[0]), "r"(a[1]), "r"(a[2]), "r"(a[3]), "r"(b[0]), "r"(b[1]));
}

// stage tile loader: 128 rows x 32 bf16 (64B rows), swizzled 16B chunks
__device__ __forceinline__ void issue_tile(uint32_t smem_tile,
                                           const __nv_bfloat16* __restrict__ G,
                                           int row0, int k0, int K, int tid)
{
#pragma unroll
    for (int t = 0; t < 2; t++) {
        int id = tid + t * 256;        // 0..511
        int r  = id >> 2;              // 0..127
        int c  = id & 3;               // 16B chunk
        int pc = c ^ ((r >> 1) & 3);
        cp_async16(smem_tile + r * 64 + pc * 16,
                   G + (size_t)(row0 + r) * K + k0 + c * 8);
    }
}

__global__ __launch_bounds__(256, 1) void gemm_mma(
    const __nv_bfloat16* __restrict__ Ah, const __nv_bfloat16* __restrict__ Al,
    const __nv_bfloat16* __restrict__ Bh, const __nv_bfloat16* __restrict__ Bl,
    const float* __restrict__ bias, float* __restrict__ C, int M, int N, int K)
{
    extern __shared__ char smc[];
    const uint32_t sb = smem_u32(smc);
    const int tid = threadIdx.x;
    const int lane = tid & 31;
    const int wid = tid >> 5;
    const int wm = wid & 1;            // 0..1 -> 64-row block
    const int wn = wid >> 1;           // 0..3 -> 32-col block
    const int m0 = blockIdx.y * 128;
    const int n0 = blockIdx.x * 128;

    const int S = K >> 5;              // 32-wide K chunks

    // prologue: stages 0, 1
#pragma unroll
    for (int s = 0; s < 2; s++) {
        uint32_t base = sb + s * GM_STAGE;
        issue_tile(base + 0 * GM_TILE_BYTES, Ah, m0, s * 32, K, tid);
        issue_tile(base + 1 * GM_TILE_BYTES, Al, m0, s * 32, K, tid);
        issue_tile(base + 2 * GM_TILE_BYTES, Bh, n0, s * 32, K, tid);
        issue_tile(base + 3 * GM_TILE_BYTES, Bl, n0, s * 32, K, tid);
        cp_commit();
    }

    float acc[4][4][4];
#pragma unroll
    for (int i = 0; i < 4; i++)
#pragma unroll
        for (int j = 0; j < 4; j++)
#pragma unroll
            for (int r = 0; r < 4; r++) acc[i][j][r] = 0.f;

    // precomputed intra-tile fragment offsets
    // A: row = wm*64 + mt*16 + (lane&15); chunk = ks*2 + (lane>>4)
    const int a_r = wm * 64 + (lane & 15);
    const int a_c = (lane >> 4);
    // B: row = wn*32 + g*16 + (lane&7) + ((lane>>4)&1)*8 ... see mapping below
    const int b_sub = lane >> 3;            // 0..3
    const int b_r = wn * 32 + (lane & 7) + (b_sub >> 1) * 8;
    const int b_c = (b_sub & 1);

    for (int s = 0; s < S; s++) {
        cp_wait1();
        __syncthreads();

        const uint32_t base = sb + (s & 1) * GM_STAGE;
        const uint32_t tAh = base;
        const uint32_t tAl = base + GM_TILE_BYTES;
        const uint32_t tBh = base + 2 * GM_TILE_BYTES;
        const uint32_t tBl = base + 3 * GM_TILE_BYTES;

#pragma unroll
        for (int ks = 0; ks < 2; ks++) {
            uint32_t ah[4][4], al[4][4], bh[4][2], bl[4][2];
            // A fragments: 4 m-tiles
#pragma unroll
            for (int mt = 0; mt < 4; mt++) {
                int r = a_r + mt * 16;
                int pc = (ks * 2 + a_c) ^ ((r >> 1) & 3);
                uint32_t off = r * 64 + pc * 16;
                ldm_x4(ah[mt], tAh + off);
                ldm_x4(al[mt], tAl + off);
            }
            // B fragments: 2 groups of 16 n-rows -> 4 n-tiles
#pragma unroll
            for (int g = 0; g < 2; g++) {
                int r = b_r + g * 16;
                int pc = (ks * 2 + b_c) ^ ((r >> 1) & 3);
                uint32_t off = r * 64 + pc * 16;
                uint32_t th[4], tl[4];
                ldm_x4(th, tBh + off);
                ldm_x4(tl, tBl + off);
                bh[g * 2][0] = th[0]; bh[g * 2][1] = th[1];
                bh[g * 2 + 1][0] = th[2]; bh[g * 2 + 1][1] = th[3];
                bl[g * 2][0] = tl[0]; bl[g * 2][1] = tl[1];
                bl[g * 2 + 1][0] = tl[2]; bl[g * 2 + 1][1] = tl[3];
            }
            // 3-pass MMAs
#pragma unroll
            for (int mt = 0; mt < 4; mt++)
#pragma unroll
                for (int nt = 0; nt < 4; nt++) {
                    mma_bf16(acc[mt][nt], ah[mt], bh[nt]);
                    mma_bf16(acc[mt][nt], al[mt], bh[nt]);
                    mma_bf16(acc[mt][nt], ah[mt], bl[nt]);
                }
        }
        __syncthreads();
        if (s + 2 < S) {
            uint32_t nbase = sb + (s & 1) * GM_STAGE;
            int k0 = (s + 2) * 32;
            issue_tile(nbase + 0 * GM_TILE_BYTES, Ah, m0, k0, K, tid);
            issue_tile(nbase + 1 * GM_TILE_BYTES, Al, m0, k0, K, tid);
            issue_tile(nbase + 2 * GM_TILE_BYTES, Bh, n0, k0, K, tid);
            issue_tile(nbase + 3 * GM_TILE_BYTES, Bl, n0, k0, K, tid);
        }
        cp_commit();
    }

    // epilogue: acc -> C with bias
    const int cm = m0 + wm * 64 + (lane >> 2);
    const int cn = n0 + wn * 32 + (lane & 3) * 2;
#pragma unroll
    for (int nt = 0; nt < 4; nt++) {
        float b0 = bias[cn + nt * 8];
        float b1 = bias[cn + nt * 8 + 1];
#pragma unroll
        for (int mt = 0; mt < 4; mt++) {
            float* r0 = C + (size_t)(cm + mt * 16) * N + cn + nt * 8;
            float* r1 = r0 + 8 * N;
            float2 o0 = make_float2(acc[mt][nt][0] + b0, acc[mt][nt][1] + b1);
            float2 o1 = make_float2(acc[mt][nt][2] + b0, acc[mt][nt][3] + b1);
            *(float2*)r0 = o0;
            *(float2*)r1 = o1;
        }
    }
}

// ---------------------------------------------------------------------------
// Fused attention (unchanged from R1 passing kernel)
// ---------------------------------------------------------------------------
#define AT_BQ 128
#define AT_BK 64
#define KS_STRIDE 132
#define SS_STRIDE 68
#define ATT_SMEM_FLOATS (128*128 + 64*KS_STRIDE + 64*128 + 128*SS_STRIDE + 3*128)
#define ATT_SMEM_BYTES (ATT_SMEM_FLOATS * 4)

__global__ __launch_bounds__(256, 1) void attn_kernel(
    const float* __restrict__ qkv, const float* __restrict__ biasM,
    float* __restrict__ ctxOut)
{
    extern __shared__ float sm[];
    float* Qs   = sm;
    float* Ks   = Qs + 128 * 128;
    float* Vs   = Ks + 64 * KS_STRIDE;
    float* Ss   = Vs + 64 * 128;
    float* sm_m = Ss + 128 * SS_STRIDE;
    float* sm_l = sm_m + 128;
    float* sm_a = sm_l + 128;

    const int tid = threadIdx.x;
    const int tx = tid & 15, ty = tid >> 4;
    const int h  = blockIdx.y;
    const int q0 = blockIdx.x * AT_BQ;

    {
        const float* qbase = qkv + (size_t)q0 * E3 + h * D_HEAD;
#pragma unroll
        for (int i = 0; i < 16; i++) {
            int f = tid + i * 256;
            int r = f >> 5;
            int c = (f & 31) * 4;
            *(float4*)&Qs[r * 128 + c] = *(const float4*)(qbase + (size_t)r * E3 + c);
        }
    }
    if (tid < 128) { sm_m[tid] = -INFINITY; sm_l[tid] = 0.f; }

    float ctx[8][8];
#pragma unroll
    for (int i = 0; i < 8; i++)
#pragma unroll
        for (int j = 0; j < 8; j++) ctx[i][j] = 0.f;

    const float scale = 0.088388347648318447f;

    for (int kt = 0; kt < L_SEQ / AT_BK; kt++) {
        const int k0 = kt * AT_BK;
        __syncthreads();

        {
            const float* kbase = qkv + (size_t)k0 * E3 + E_DIM     + h * D_HEAD;
            const float* vbase = qkv + (size_t)k0 * E3 + 2 * E_DIM + h * D_HEAD;
#pragma unroll
            for (int i = 0; i < 8; i++) {
                int f = tid + i * 256;
                int r = f >> 5;
                int c = (f & 31) * 4;
                *(float4*)&Ks[r * KS_STRIDE + c] = *(const float4*)(kbase + (size_t)r * E3 + c);
                *(float4*)&Vs[r * 128 + c]       = *(const float4*)(vbase + (size_t)r * E3 + c);
            }
        }
        __syncthreads();

        float sacc[8][4];
#pragma unroll
        for (int i = 0; i < 8; i++)
#pragma unroll
            for (int j = 0; j < 4; j++) sacc[i][j] = 0.f;

#pragma unroll 2
        for (int d4 = 0; d4 < 32; d4++) {
            float4 q[8];
#pragma unroll
            for (int i = 0; i < 8; i++)
                q[i] = *(const float4*)&Qs[(ty * 8 + i) * 128 + d4 * 4];
#pragma unroll
            for (int dd = 0; dd < 4; dd++) {
                float kv[4];
#pragma unroll
                for (int j = 0; j < 4; j++)
                    kv[j] = Ks[(tx + 16 * j) * KS_STRIDE + d4 * 4 + dd];
#pragma unroll
                for (int i = 0; i < 8; i++) {
                    float qv = (dd == 0) ? q[i].x : (dd == 1) ? q[i].y
                             : (dd == 2) ? q[i].z : q[i].w;
#pragma unroll
                    for (int j = 0; j < 4; j++)
                        sacc[i][j] = fmaf(qv, kv[j], sacc[i][j]);
                }
            }
        }

#pragma unroll
        for (int i = 0; i < 8; i++) {
            int qr = ty * 8 + i;
            const float* brow = biasM + (size_t)(q0 + qr) * L_SEQ + k0;
#pragma unroll
            for (int j = 0; j < 4; j++) {
                int kc = tx + 16 * j;
                Ss[qr * SS_STRIDE + kc] = fmaf(sacc[i][j], scale, brow[kc]);
            }
        }
        __syncthreads();

        {
            int row = tid >> 1, half = tid & 1;
            float* srow = &Ss[row * SS_STRIDE + half * 32];
            float mloc = -INFINITY;
#pragma unroll
            for (int c = 0; c < 32; c++) mloc = fmaxf(mloc, srow[c]);
            mloc = fmaxf(mloc, __shfl_xor_sync(0xffffffffu, mloc, 1));
            float mold = sm_m[row];
            float mnew = fmaxf(mold, mloc);
            float ssum = 0.f;
#pragma unroll
            for (int c = 0; c < 32; c++) {
                float p = __expf(srow[c] - mnew);
                srow[c] = p;
                ssum += p;
            }
            ssum += __shfl_xor_sync(0xffffffffu, ssum, 1);
            if (half == 0) {
                float alpha = __expf(mold - mnew);
                sm_m[row] = mnew;
                sm_a[row] = alpha;
                sm_l[row] = sm_l[row] * alpha + ssum;
            }
        }
        __syncthreads();

        float al[8];
#pragma unroll
        for (int i = 0; i < 8; i++) al[i] = sm_a[ty * 8 + i];
#pragma unroll
        for (int i = 0; i < 8; i++)
#pragma unroll
            for (int j = 0; j < 8; j++) ctx[i][j] *= al[i];

#pragma unroll 4
        for (int kk = 0; kk < AT_BK; kk++) {
            float p[8];
#pragma unroll
            for (int i = 0; i < 8; i++) p[i] = Ss[(ty * 8 + i) * SS_STRIDE + kk];
            float4 v0 = *(const float4*)&Vs[kk * 128 + tx * 8];
            float4 v1 = *(const float4*)&Vs[kk * 128 + tx * 8 + 4];
            float v[8] = {v0.x, v0.y, v0.z, v0.w, v1.x, v1.y, v1.z, v1.w};
#pragma unroll
            for (int i = 0; i < 8; i++)
#pragma unroll
                for (int j = 0; j < 8; j++)
                    ctx[i][j] = fmaf(p[i], v[j], ctx[i][j]);
        }
    }

#pragma unroll
    for (int i = 0; i < 8; i++) {
        int qr = ty * 8 + i;
        float inv = 1.0f / sm_l[qr];
        float4 o0 = make_float4(ctx[i][0] * inv, ctx[i][1] * inv,
                                ctx[i][2] * inv, ctx[i][3] * inv);
        float4 o1 = make_float4(ctx[i][4] * inv, ctx[i][5] * inv,
                                ctx[i][6] * inv, ctx[i][7] * inv);
        float* dst = ctxOut + (size_t)(q0 + qr) * E_DIM + h * D_HEAD + tx * 8;
        *(float4*)dst       = o0;
        *(float4*)(dst + 4) = o1;
    }
}

// ---------------------------------------------------------------------------
extern "C" void kernel_launch(void* const* d_in, const int* in_sizes, int n_in,
                              void* d_out, int out_size)
{
    const float* x     = (const float*)d_in[0];
    const float* biasM = (const float*)d_in[1];
    const float* w_in  = (const float*)d_in[2];
    const float* b_in  = (const float*)d_in[3];
    const float* w_out = (const float*)d_in[4];
    const float* b_out = (const float*)d_in[5];
    float* out = (float*)d_out;

    float *qkv_p, *ctx_p;
    __nv_bfloat16 *xh, *xl, *wih, *wil, *woh, *wol, *ch, *cl;
    cudaGetSymbolAddress((void**)&qkv_p, g_qkv);
    cudaGetSymbolAddress((void**)&ctx_p, g_ctx);
    cudaGetSymbolAddress((void**)&xh, g_xh);
    cudaGetSymbolAddress((void**)&xl, g_xl);
    cudaGetSymbolAddress((void**)&wih, g_wih);
    cudaGetSymbolAddress((void**)&wil, g_wil);
    cudaGetSymbolAddress((void**)&woh, g_woh);
    cudaGetSymbolAddress((void**)&wol, g_wol);
    cudaGetSymbolAddress((void**)&ch, g_ch);
    cudaGetSymbolAddress((void**)&cl, g_cl);

    cudaFuncSetAttribute(attn_kernel, cudaFuncAttributeMaxDynamicSharedMemorySize,
                         ATT_SMEM_BYTES);
    cudaFuncSetAttribute(gemm_mma, cudaFuncAttributeMaxDynamicSharedMemorySize, GM_SMEM);

    // split fp32 -> bf16 hi/lo
    {
        int n4 = (L_SEQ * E_DIM) / 4;
        split_bf16_kernel<<<(n4 + 255) / 256, 256>>>(x, xh, xl, n4);
        int w4 = (E3 * E_DIM) / 4;
        split_bf16_kernel<<<(w4 + 255) / 256, 256>>>(w_in, wih, wil, w4);
        int o4 = (E_DIM * E_DIM) / 4;
        split_bf16_kernel<<<(o4 + 255) / 256, 256>>>(w_out, woh, wol, o4);
    }

    // 1) QKV = x @ W_in^T + b_in   [2048, 6144]
    gemm_mma<<<dim3(E3 / 128, L_SEQ / 128), 256, GM_SMEM>>>(
        xh, xl, wih, wil, b_in, qkv_p, L_SEQ, E3, E_DIM);

    // 2) Fused attention -> ctx [2048, 2048]
    attn_kernel<<<dim3(L_SEQ / AT_BQ, H_NUM), 256, ATT_SMEM_BYTES>>>(
        qkv_p, biasM, ctx_p);

    // split ctx for GEMM2
    {
        int c4 = (L_SEQ * E_DIM) / 4;
        split_bf16_kernel<<<(c4 + 255) / 256, 256>>>(ctx_p, ch, cl, c4);
    }

    // 3) out = ctx @ W_out^T + b_out   [2048, 2048]
    gemm_mma<<<dim3(E_DIM / 128, L_SEQ / 128), 256, GM_SMEM>>>(
        ch, cl, woh, wol, b_out, out, L_SEQ, E_DIM, E_DIM);
}

// round 4
// speedup vs baseline: 2.6542x; 1.6114x over previous
#include <cuda_runtime.h>
#include <cuda_bf16.h>
#include <cstdint>
#include <math.h>

#define L_SEQ 2048
#define E_DIM 2048
#define H_NUM 16
#define D_HEAD 128
#define E3 6144

// ---------------------------------------------------------------------------
// Device-global scratch (allocation-free rule)
// ---------------------------------------------------------------------------
__device__ __align__(16) __nv_bfloat16 g_xh[L_SEQ * E_DIM];
__device__ __align__(16) __nv_bfloat16 g_xl[L_SEQ * E_DIM];
__device__ __align__(16) __nv_bfloat16 g_wih[E3 * E_DIM];
__device__ __align__(16) __nv_bfloat16 g_wil[E3 * E_DIM];
__device__ __align__(16) __nv_bfloat16 g_woh[E_DIM * E_DIM];
__device__ __align__(16) __nv_bfloat16 g_wol[E_DIM * E_DIM];
__device__ __align__(16) __nv_bfloat16 g_qkvh[L_SEQ * E3];
__device__ __align__(16) __nv_bfloat16 g_qkvl[L_SEQ * E3];
__device__ __align__(16) __nv_bfloat16 g_ch[L_SEQ * E_DIM];
__device__ __align__(16) __nv_bfloat16 g_cl[L_SEQ * E_DIM];

__device__ __forceinline__ uint32_t smem_u32(const void* p) {
    uint32_t a;
    asm("{ .reg .u64 t; cvta.to.shared.u64 t, %1; cvt.u32.u64 %0, t; }" : "=r"(a) : "l"(p));
    return a;
}
__device__ __forceinline__ void cp_async16(uint32_t dst, const void* src) {
    asm volatile("cp.async.cg.shared.global [%0], [%1], 16;" :: "r"(dst), "l"(src));
}
__device__ __forceinline__ void cp_commit() {
    asm volatile("cp.async.commit_group;" ::: "memory");
}
__device__ __forceinline__ void cp_wait1() {
    asm volatile("cp.async.wait_group 1;" ::: "memory");
}
__device__ __forceinline__ void cp_wait0() {
    asm volatile("cp.async.wait_group 0;" ::: "memory");
}
__device__ __forceinline__ void ldm_x4(uint32_t* r, uint32_t addr) {
    asm volatile("ldmatrix.sync.aligned.m8n8.x4.shared.b16 {%0,%1,%2,%3}, [%4];"
                 : "=r"(r[0]), "=r"(r[1]), "=r"(r[2]), "=r"(r[3]) : "r"(addr));
}
__device__ __forceinline__ void ldm_x4_t(uint32_t* r, uint32_t addr) {
    asm volatile("ldmatrix.sync.aligned.m8n8.x4.trans.shared.b16 {%0,%1,%2,%3}, [%4];"
                 : "=r"(r[0]), "=r"(r[1]), "=r"(r[2]), "=r"(r[3]) : "r"(addr));
}
__device__ __forceinline__ void mma_bf16(float* c, const uint32_t* a, const uint32_t* b) {
    asm volatile(
        "mma.sync.aligned.m16n8k16.row.col.f32.bf16.bf16.f32 "
        "{%0,%1,%2,%3}, {%4,%5,%6,%7}, {%8,%9}, {%0,%1,%2,%3};"
        : "+f"(c[0]), "+f"(c[1]), "+f"(c[2]), "+f"(c[3])
        : "r"(a[0]), "r"(a[1]), "r"(a[2]), "r"(a[3]), "r"(b[0]), "r"(b[1]));
}
__device__ __forceinline__ uint32_t pack_bf2(__nv_bfloat16 a, __nv_bfloat16 b) {
    __nv_bfloat162 t(a, b);
    return *reinterpret_cast<uint32_t*>(&t);
}
// exp2 polynomial (degree-6 Taylor, rel err <= ~3e-5), FMA-pipe only
__device__ __forceinline__ float exp2p(float t) {
    t = fmaxf(t, -126.f);
    float fl = floorf(t);
    float f = t - fl;
    float p = 1.5403530e-4f;
    p = fmaf(p, f, 1.3333558e-3f);
    p = fmaf(p, f, 9.6181291e-3f);
    p = fmaf(p, f, 5.5504109e-2f);
    p = fmaf(p, f, 2.4022651e-1f);
    p = fmaf(p, f, 6.9314718e-1f);
    p = fmaf(p, f, 1.0f);
    return p * __int_as_float(((int)fl + 127) << 23);
}

// ---------------------------------------------------------------------------
// fp32 -> split bf16 (hi + lo)
// ---------------------------------------------------------------------------
__global__ void split_bf16_kernel(const float* __restrict__ in,
                                  __nv_bfloat16* __restrict__ hi,
                                  __nv_bfloat16* __restrict__ lo, int n4)
{
    int i = blockIdx.x * blockDim.x + threadIdx.x;
    if (i >= n4) return;
    float4 v = ((const float4*)in)[i];
    __nv_bfloat16 hx = __float2bfloat16(v.x);
    __nv_bfloat16 hy = __float2bfloat16(v.y);
    __nv_bfloat16 hz = __float2bfloat16(v.z);
    __nv_bfloat16 hw = __float2bfloat16(v.w);
    __nv_bfloat16 lx = __float2bfloat16(v.x - __bfloat162float(hx));
    __nv_bfloat16 ly = __float2bfloat16(v.y - __bfloat162float(hy));
    __nv_bfloat16 lz = __float2bfloat16(v.z - __bfloat162float(hz));
    __nv_bfloat16 lw = __float2bfloat16(v.w - __bfloat162float(hw));
    ((__nv_bfloat162*)hi)[2 * i]     = __nv_bfloat162(hx, hy);
    ((__nv_bfloat162*)hi)[2 * i + 1] = __nv_bfloat162(hz, hw);
    ((__nv_bfloat162*)lo)[2 * i]     = __nv_bfloat162(lx, ly);
    ((__nv_bfloat162*)lo)[2 * i + 1] = __nv_bfloat162(lz, lw);
}

// ---------------------------------------------------------------------------
// Split-bf16 mma.sync GEMM: C = A @ B^T + bias. Optionally writes split
// bf16 hi/lo output (Ch/Cl) instead of fp32 (Cf).
// ---------------------------------------------------------------------------
#define GM_TILE_BYTES 8192
#define GM_STAGE (4 * GM_TILE_BYTES)
#define GM_SMEM (2 * GM_STAGE)

__device__ __forceinline__ void issue_tile(uint32_t smem_tile,
                                           const __nv_bfloat16* __restrict__ G,
                                           int row0, int k0, int K, int tid)
{
#pragma unroll
    for (int t = 0; t < 2; t++) {
        int id = tid + t * 256;
        int r  = id >> 2;
        int c  = id & 3;
        int pc = c ^ ((r >> 1) & 3);
        cp_async16(smem_tile + r * 64 + pc * 16,
                   G + (size_t)(row0 + r) * K + k0 + c * 8);
    }
}

__global__ __launch_bounds__(256, 1) void gemm_mma(
    const __nv_bfloat16* __restrict__ Ah, const __nv_bfloat16* __restrict__ Al,
    const __nv_bfloat16* __restrict__ Bh, const __nv_bfloat16* __restrict__ Bl,
    const float* __restrict__ bias, float* __restrict__ Cf,
    __nv_bfloat16* __restrict__ Ch, __nv_bfloat16* __restrict__ Cl,
    int M, int N, int K)
{
    extern __shared__ char smc[];
    const uint32_t sb = smem_u32(smc);
    const int tid = threadIdx.x;
    const int lane = tid & 31;
    const int wid = tid >> 5;
    const int wm = wid & 1;
    const int wn = wid >> 1;
    const int m0 = blockIdx.y * 128;
    const int n0 = blockIdx.x * 128;

    const int S = K >> 5;

#pragma unroll
    for (int s = 0; s < 2; s++) {
        uint32_t base = sb + s * GM_STAGE;
        issue_tile(base + 0 * GM_TILE_BYTES, Ah, m0, s * 32, K, tid);
        issue_tile(base + 1 * GM_TILE_BYTES, Al, m0, s * 32, K, tid);
        issue_tile(base + 2 * GM_TILE_BYTES, Bh, n0, s * 32, K, tid);
        issue_tile(base + 3 * GM_TILE_BYTES, Bl, n0, s * 32, K, tid);
        cp_commit();
    }

    float acc[4][4][4];
#pragma unroll
    for (int i = 0; i < 4; i++)
#pragma unroll
        for (int j = 0; j < 4; j++)
#pragma unroll
            for (int r = 0; r < 4; r++) acc[i][j][r] = 0.f;

    const int a_r = wm * 64 + (lane & 15);
    const int a_c = (lane >> 4);
    const int b_sub = lane >> 3;
    const int b_r = wn * 32 + (lane & 7) + (b_sub >> 1) * 8;
    const int b_c = (b_sub & 1);

    for (int s = 0; s < S; s++) {
        cp_wait1();
        __syncthreads();

        const uint32_t base = sb + (s & 1) * GM_STAGE;
        const uint32_t tAh = base;
        const uint32_t tAl = base + GM_TILE_BYTES;
        const uint32_t tBh = base + 2 * GM_TILE_BYTES;
        const uint32_t tBl = base + 3 * GM_TILE_BYTES;

#pragma unroll
        for (int ks = 0; ks < 2; ks++) {
            uint32_t ah[4][4], al[4][4], bh[4][2], bl[4][2];
#pragma unroll
            for (int mt = 0; mt < 4; mt++) {
                int r = a_r + mt * 16;
                int pc = (ks * 2 + a_c) ^ ((r >> 1) & 3);
                uint32_t off = r * 64 + pc * 16;
                ldm_x4(ah[mt], tAh + off);
                ldm_x4(al[mt], tAl + off);
            }
#pragma unroll
            for (int g = 0; g < 2; g++) {
                int r = b_r + g * 16;
                int pc = (ks * 2 + b_c) ^ ((r >> 1) & 3);
                uint32_t off = r * 64 + pc * 16;
                uint32_t th[4], tl[4];
                ldm_x4(th, tBh + off);
                ldm_x4(tl, tBl + off);
                bh[g * 2][0] = th[0]; bh[g * 2][1] = th[1];
                bh[g * 2 + 1][0] = th[2]; bh[g * 2 + 1][1] = th[3];
                bl[g * 2][0] = tl[0]; bl[g * 2][1] = tl[1];
                bl[g * 2 + 1][0] = tl[2]; bl[g * 2 + 1][1] = tl[3];
            }
#pragma unroll
            for (int mt = 0; mt < 4; mt++)
#pragma unroll
                for (int nt = 0; nt < 4; nt++) {
                    mma_bf16(acc[mt][nt], ah[mt], bh[nt]);
                    mma_bf16(acc[mt][nt], al[mt], bh[nt]);
                    mma_bf16(acc[mt][nt], ah[mt], bl[nt]);
                }
        }
        __syncthreads();
        if (s + 2 < S) {
            uint32_t nbase = sb + (s & 1) * GM_STAGE;
            int k0 = (s + 2) * 32;
            issue_tile(nbase + 0 * GM_TILE_BYTES, Ah, m0, k0, K, tid);
            issue_tile(nbase + 1 * GM_TILE_BYTES, Al, m0, k0, K, tid);
            issue_tile(nbase + 2 * GM_TILE_BYTES, Bh, n0, k0, K, tid);
            issue_tile(nbase + 3 * GM_TILE_BYTES, Bl, n0, k0, K, tid);
        }
        cp_commit();
    }

    const int cm = m0 + wm * 64 + (lane >> 2);
    const int cn = n0 + wn * 32 + (lane & 3) * 2;
    if (Cf) {
#pragma unroll
        for (int nt = 0; nt < 4; nt++) {
            float b0 = bias[cn + nt * 8];
            float b1 = bias[cn + nt * 8 + 1];
#pragma unroll
            for (int mt = 0; mt < 4; mt++) {
                float* r0 = Cf + (size_t)(cm + mt * 16) * N + cn + nt * 8;
                float* r1 = r0 + 8 * N;
                *(float2*)r0 = make_float2(acc[mt][nt][0] + b0, acc[mt][nt][1] + b1);
                *(float2*)r1 = make_float2(acc[mt][nt][2] + b0, acc[mt][nt][3] + b1);
            }
        }
    } else {
#pragma unroll
        for (int nt = 0; nt < 4; nt++) {
            float b0 = bias[cn + nt * 8];
            float b1 = bias[cn + nt * 8 + 1];
#pragma unroll
            for (int mt = 0; mt < 4; mt++) {
#pragma unroll
                for (int half = 0; half < 2; half++) {
                    float v0 = acc[mt][nt][2 * half + 0] + b0;
                    float v1 = acc[mt][nt][2 * half + 1] + b1;
                    __nv_bfloat16 h0 = __float2bfloat16(v0);
                    __nv_bfloat16 h1 = __float2bfloat16(v1);
                    __nv_bfloat16 l0 = __float2bfloat16(v0 - __bfloat162float(h0));
                    __nv_bfloat16 l1 = __float2bfloat16(v1 - __bfloat162float(h1));
                    size_t off = (size_t)(cm + mt * 16 + half * 8) * N + cn + nt * 8;
                    *(uint32_t*)(Ch + off) = pack_bf2(h0, h1);
                    *(uint32_t*)(Cl + off) = pack_bf2(l0, l1);
                }
            }
        }
    }
}

// ---------------------------------------------------------------------------
// Tensor-core flash attention with split-bf16 3-pass for S and P@V.
// CTA = (128 q-rows, head). 8 warps x 16 q-rows. BK = 64.
// smem: 2 stages x {Kh,Kl,Vh,Vl}[64x128 bf16], rows 256B, chunk swizzle c^(r&7)
// ---------------------------------------------------------------------------
#define ATT_STAGE 65536
#define ATT_SMEM (2 * ATT_STAGE)
#define ATT_NT 32  // k-tiles

__device__ __forceinline__ uint32_t sw_addr(uint32_t base, int r, int c) {
    return base + r * 256 + ((c ^ (r & 7)) << 4);
}
__device__ __forceinline__ void att_load_tile(uint32_t dst,
                                              const __nv_bfloat16* __restrict__ g,
                                              int k0, int tid)
{
#pragma unroll
    for (int i = 0; i < 4; i++) {
        int id = tid + i * 256;
        int r = id >> 4;
        int c = id & 15;
        cp_async16(sw_addr(dst, r, c), g + (size_t)(k0 + r) * E3 + c * 8);
    }
}

__global__ __launch_bounds__(256, 1) void attn_tc(
    const __nv_bfloat16* __restrict__ qkvh, const __nv_bfloat16* __restrict__ qkvl,
    const float* __restrict__ biasM,
    __nv_bfloat16* __restrict__ ch, __nv_bfloat16* __restrict__ cl)
{
    extern __shared__ char smc[];
    const uint32_t sb = smem_u32(smc);
    const int tid = threadIdx.x;
    const int lane = tid & 31;
    const int wid = tid >> 5;
    const int h = blockIdx.y;
    const int q0 = blockIdx.x * 128;

    const uint32_t buf0 = sb;
    const uint32_t buf1 = sb + ATT_STAGE;

    const __nv_bfloat16* gKh = qkvh + E_DIM + h * D_HEAD;
    const __nv_bfloat16* gKl = qkvl + E_DIM + h * D_HEAD;
    const __nv_bfloat16* gVh = qkvh + 2 * E_DIM + h * D_HEAD;
    const __nv_bfloat16* gVl = qkvl + 2 * E_DIM + h * D_HEAD;

    // Q (h/l) -> buf0 (32KB + 32KB)
    {
        const __nv_bfloat16* gqh = qkvh + (size_t)q0 * E3 + h * D_HEAD;
        const __nv_bfloat16* gql = qkvl + (size_t)q0 * E3 + h * D_HEAD;
#pragma unroll
        for (int i = 0; i < 8; i++) {
            int id = tid + i * 256;
            int r = id >> 4;
            int c = id & 15;
            cp_async16(sw_addr(buf0, r, c), gqh + (size_t)r * E3 + c * 8);
        }
#pragma unroll
        for (int i = 0; i < 8; i++) {
            int id = tid + i * 256;
            int r = id >> 4;
            int c = id & 15;
            cp_async16(sw_addr(buf0 + 32768, r, c), gql + (size_t)r * E3 + c * 8);
        }
        cp_commit();
    }
    // k-tile 0 -> buf1
    att_load_tile(buf1 + 0,     gKh, 0, tid);
    att_load_tile(buf1 + 16384, gKl, 0, tid);
    att_load_tile(buf1 + 32768, gVh, 0, tid);
    att_load_tile(buf1 + 49152, gVl, 0, tid);
    cp_commit();

    cp_wait1();            // Q ready
    __syncthreads();

    // extract Q fragments (register-resident for the whole kernel)
    uint32_t qh_f[8][4], ql_f[8][4];
    {
        int r = wid * 16 + (lane & 15);
#pragma unroll
        for (int kf = 0; kf < 8; kf++) {
            int c = 2 * kf + (lane >> 4);
            ldm_x4(qh_f[kf], sw_addr(buf0, r, c));
            ldm_x4(ql_f[kf], sw_addr(buf0 + 32768, r, c));
        }
    }
    __syncthreads();       // all warps done with Q region

    // k-tile 1 -> buf0
    att_load_tile(buf0 + 0,     gKh, 64, tid);
    att_load_tile(buf0 + 16384, gKl, 64, tid);
    att_load_tile(buf0 + 32768, gVh, 64, tid);
    att_load_tile(buf0 + 49152, gVl, 64, tid);
    cp_commit();

    float mA = -INFINITY, mB = -INFINITY, lA = 0.f, lB = 0.f;
    float ctx[16][4];
#pragma unroll
    for (int i = 0; i < 16; i++)
#pragma unroll
        for (int j = 0; j < 4; j++) ctx[i][j] = 0.f;

    const float SCALE = 0.088388347648318447f;
    const float LOG2E = 1.4426950408889634f;
    const int rA = q0 + wid * 16 + (lane >> 2);
    const int rB = rA + 8;
    const int cb = 2 * (lane & 3);

    const int s_br = (lane & 7) + ((lane >> 4) & 1) * 8;
    const int s_bc = (lane >> 3) & 1;
    const int a_r = (lane & 15);
    const int a_c = (lane >> 4);

    for (int kt = 0; kt < ATT_NT; kt++) {
        if (kt < ATT_NT - 2) cp_wait1(); else cp_wait0();
        __syncthreads();
        const uint32_t buf = (kt & 1) ? buf0 : buf1;
        const int k0 = kt * 64;

        // ---- S = scale * Q @ K^T + bias (3-pass split)
        float sacc[8][4];
#pragma unroll
        for (int i = 0; i < 8; i++)
#pragma unroll
            for (int j = 0; j < 4; j++) sacc[i][j] = 0.f;

#pragma unroll
        for (int kf = 0; kf < 8; kf++) {
#pragma unroll
            for (int ng = 0; ng < 4; ng++) {
                int r = ng * 16 + s_br;
                int c = 2 * kf + s_bc;
                uint32_t th[4], tl[4];
                ldm_x4(th, sw_addr(buf + 0, r, c));
                ldm_x4(tl, sw_addr(buf + 16384, r, c));
                uint32_t bh0[2] = {th[0], th[1]}, bh1[2] = {th[2], th[3]};
                uint32_t bl0[2] = {tl[0], tl[1]}, bl1[2] = {tl[2], tl[3]};
                mma_bf16(sacc[2 * ng],     qh_f[kf], bh0);
                mma_bf16(sacc[2 * ng],     ql_f[kf], bh0);
                mma_bf16(sacc[2 * ng],     qh_f[kf], bl0);
                mma_bf16(sacc[2 * ng + 1], qh_f[kf], bh1);
                mma_bf16(sacc[2 * ng + 1], ql_f[kf], bh1);
                mma_bf16(sacc[2 * ng + 1], qh_f[kf], bl1);
            }
        }

        // ---- scale + bias, online softmax (per-warp local rows)
        float mxA = -INFINITY, mxB = -INFINITY;
#pragma unroll
        for (int nt = 0; nt < 8; nt++) {
            float2 bA = *(const float2*)(biasM + (size_t)rA * L_SEQ + k0 + nt * 8 + cb);
            float2 bB = *(const float2*)(biasM + (size_t)rB * L_SEQ + k0 + nt * 8 + cb);
            sacc[nt][0] = fmaf(sacc[nt][0], SCALE, bA.x);
            sacc[nt][1] = fmaf(sacc[nt][1], SCALE, bA.y);
            sacc[nt][2] = fmaf(sacc[nt][2], SCALE, bB.x);
            sacc[nt][3] = fmaf(sacc[nt][3], SCALE, bB.y);
            mxA = fmaxf(mxA, fmaxf(sacc[nt][0], sacc[nt][1]));
            mxB = fmaxf(mxB, fmaxf(sacc[nt][2], sacc[nt][3]));
        }
        mxA = fmaxf(mxA, __shfl_xor_sync(0xffffffffu, mxA, 1));
        mxA = fmaxf(mxA, __shfl_xor_sync(0xffffffffu, mxA, 2));
        mxB = fmaxf(mxB, __shfl_xor_sync(0xffffffffu, mxB, 1));
        mxB = fmaxf(mxB, __shfl_xor_sync(0xffffffffu, mxB, 2));
        float mnA = fmaxf(mA, mxA), mnB = fmaxf(mB, mxB);
        float alA = exp2p((mA - mnA) * LOG2E);
        float alB = exp2p((mB - mnB) * LOG2E);
        float negA = mnA * LOG2E, negB = mnB * LOG2E;
        float sumA = 0.f, sumB = 0.f;
#pragma unroll
        for (int nt = 0; nt < 8; nt++) {
            sacc[nt][0] = exp2p(fmaf(sacc[nt][0], LOG2E, -negA));
            sacc[nt][1] = exp2p(fmaf(sacc[nt][1], LOG2E, -negA));
            sacc[nt][2] = exp2p(fmaf(sacc[nt][2], LOG2E, -negB));
            sacc[nt][3] = exp2p(fmaf(sacc[nt][3], LOG2E, -negB));
            sumA += sacc[nt][0] + sacc[nt][1];
            sumB += sacc[nt][2] + sacc[nt][3];
        }
        sumA += __shfl_xor_sync(0xffffffffu, sumA, 1);
        sumA += __shfl_xor_sync(0xffffffffu, sumA, 2);
        sumB += __shfl_xor_sync(0xffffffffu, sumB, 1);
        sumB += __shfl_xor_sync(0xffffffffu, sumB, 2);
        lA = lA * alA + sumA;
        lB = lB * alB + sumB;
        mA = mnA; mB = mnB;
#pragma unroll
        for (int nt = 0; nt < 16; nt++) {
            ctx[nt][0] *= alA; ctx[nt][1] *= alA;
            ctx[nt][2] *= alB; ctx[nt][3] *= alB;
        }

        // ---- P fragments: S accumulator layout == P@V A-operand layout
        uint32_t pah[4][4], pal[4][4];
#pragma unroll
        for (int kb = 0; kb < 4; kb++) {
#pragma unroll
            for (int half = 0; half < 2; half++) {   // half 0: rows A (c0,c1); 1: rows B (c2,c3)
#pragma unroll
                for (int sub = 0; sub < 2; sub++) {  // sub 0: nt=2kb; 1: nt=2kb+1
                    float p0 = sacc[2 * kb + sub][2 * half + 0];
                    float p1 = sacc[2 * kb + sub][2 * half + 1];
                    __nv_bfloat16 h0 = __float2bfloat16(p0);
                    __nv_bfloat16 h1 = __float2bfloat16(p1);
                    __nv_bfloat16 l0 = __float2bfloat16(p0 - __bfloat162float(h0));
                    __nv_bfloat16 l1 = __float2bfloat16(p1 - __bfloat162float(h1));
                    pah[kb][sub * 2 + half] = pack_bf2(h0, h1);
                    pal[kb][sub * 2 + half] = pack_bf2(l0, l1);
                }
            }
        }

        // ---- ctx += P @ V (3-pass split), V via ldmatrix.trans
#pragma unroll
        for (int kb = 0; kb < 4; kb++) {
#pragma unroll
            for (int db = 0; db < 8; db++) {
                int r = kb * 16 + a_r;
                int c = 2 * db + a_c;
                uint32_t th[4], tl[4];
                ldm_x4_t(th, sw_addr(buf + 32768, r, c));
                ldm_x4_t(tl, sw_addr(buf + 49152, r, c));
                uint32_t bh0[2] = {th[0], th[1]}, bh1[2] = {th[2], th[3]};
                uint32_t bl0[2] = {tl[0], tl[1]}, bl1[2] = {tl[2], tl[3]};
                mma_bf16(ctx[2 * db],     pah[kb], bh0);
                mma_bf16(ctx[2 * db],     pal[kb], bh0);
                mma_bf16(ctx[2 * db],     pah[kb], bl0);
                mma_bf16(ctx[2 * db + 1], pah[kb], bh1);
                mma_bf16(ctx[2 * db + 1], pal[kb], bh1);
                mma_bf16(ctx[2 * db + 1], pah[kb], bl1);
            }
        }

        __syncthreads();
        if (kt + 2 < ATT_NT) {
            const uint32_t nbuf = (kt & 1) ? buf0 : buf1;
            const int nk0 = (kt + 2) * 64;
            att_load_tile(nbuf + 0,     gKh, nk0, tid);
            att_load_tile(nbuf + 16384, gKl, nk0, tid);
            att_load_tile(nbuf + 32768, gVh, nk0, tid);
            att_load_tile(nbuf + 49152, gVl, nk0, tid);
            cp_commit();
        }
    }

    // ---- epilogue: normalize, split to bf16 h/l, write ctx
    float iA = 1.f / lA, iB = 1.f / lB;
#pragma unroll
    for (int nt = 0; nt < 16; nt++) {
        int col = h * D_HEAD + nt * 8 + cb;
        float v0 = ctx[nt][0] * iA, v1 = ctx[nt][1] * iA;
        float v2 = ctx[nt][2] * iB, v3 = ctx[nt][3] * iB;
        __nv_bfloat16 h0 = __float2bfloat16(v0), h1 = __float2bfloat16(v1);
        __nv_bfloat16 h2 = __float2bfloat16(v2), h3 = __float2bfloat16(v3);
        __nv_bfloat16 l0 = __float2bfloat16(v0 - __bfloat162float(h0));
        __nv_bfloat16 l1 = __float2bfloat16(v1 - __bfloat162float(h1));
        __nv_bfloat16 l2 = __float2bfloat16(v2 - __bfloat162float(h2));
        __nv_bfloat16 l3 = __float2bfloat16(v3 - __bfloat162float(h3));
        *(uint32_t*)(ch + (size_t)rA * E_DIM + col) = pack_bf2(h0, h1);
        *(uint32_t*)(cl + (size_t)rA * E_DIM + col) = pack_bf2(l0, l1);
        *(uint32_t*)(ch + (size_t)rB * E_DIM + col) = pack_bf2(h2, h3);
        *(uint32_t*)(cl + (size_t)rB * E_DIM + col) = pack_bf2(l2, l3);
    }
}

// ---------------------------------------------------------------------------
extern "C" void kernel_launch(void* const* d_in, const int* in_sizes, int n_in,
                              void* d_out, int out_size)
{
    const float* x     = (const float*)d_in[0];
    const float* biasM = (const float*)d_in[1];
    const float* w_in  = (const float*)d_in[2];
    const float* b_in  = (const float*)d_in[3];
    const float* w_out = (const float*)d_in[4];
    const float* b_out = (const float*)d_in[5];
    float* out = (float*)d_out;

    __nv_bfloat16 *xh, *xl, *wih, *wil, *woh, *wol, *qkvh, *qkvl, *ch, *cl;
    cudaGetSymbolAddress((void**)&xh, g_xh);
    cudaGetSymbolAddress((void**)&xl, g_xl);
    cudaGetSymbolAddress((void**)&wih, g_wih);
    cudaGetSymbolAddress((void**)&wil, g_wil);
    cudaGetSymbolAddress((void**)&woh, g_woh);
    cudaGetSymbolAddress((void**)&wol, g_wol);
    cudaGetSymbolAddress((void**)&qkvh, g_qkvh);
    cudaGetSymbolAddress((void**)&qkvl, g_qkvl);
    cudaGetSymbolAddress((void**)&ch, g_ch);
    cudaGetSymbolAddress((void**)&cl, g_cl);

    cudaFuncSetAttribute(gemm_mma, cudaFuncAttributeMaxDynamicSharedMemorySize, GM_SMEM);
    cudaFuncSetAttribute(attn_tc, cudaFuncAttributeMaxDynamicSharedMemorySize, ATT_SMEM);

    {
        int n4 = (L_SEQ * E_DIM) / 4;
        split_bf16_kernel<<<(n4 + 255) / 256, 256>>>(x, xh, xl, n4);
        int w4 = (E3 * E_DIM) / 4;
        split_bf16_kernel<<<(w4 + 255) / 256, 256>>>(w_in, wih, wil, w4);
        int o4 = (E_DIM * E_DIM) / 4;
        split_bf16_kernel<<<(o4 + 255) / 256, 256>>>(w_out, woh, wol, o4);
    }

    // 1) QKV projection -> split bf16 output
    gemm_mma<<<dim3(E3 / 128, L_SEQ / 128), 256, GM_SMEM>>>(
        xh, xl, wih, wil, b_in, nullptr, qkvh, qkvl, L_SEQ, E3, E_DIM);

    // 2) Tensor-core attention -> split bf16 ctx
    attn_tc<<<dim3(L_SEQ / 128, H_NUM), 256, ATT_SMEM>>>(
        qkvh, qkvl, biasM, ch, cl);

    // 3) out projection -> fp32 output
    gemm_mma<<<dim3(E_DIM / 128, L_SEQ / 128), 256, GM_SMEM>>>(
        ch, cl, woh, wol, b_out, out, nullptr, nullptr, L_SEQ, E_DIM, E_DIM);
}

// round 5
// speedup vs baseline: 2.7122x; 1.0218x over previous
#include <cuda_runtime.h>
#include <cuda_bf16.h>
#include <cstdint>
#include <math.h>

#define L_SEQ 2048
#define E_DIM 2048
#define H_NUM 16
#define D_HEAD 128
#define E3 6144

// ---------------------------------------------------------------------------
// Device-global scratch (allocation-free rule)
// ---------------------------------------------------------------------------
__device__ __align__(16) __nv_bfloat16 g_xh[L_SEQ * E_DIM];
__device__ __align__(16) __nv_bfloat16 g_xl[L_SEQ * E_DIM];
__device__ __align__(16) __nv_bfloat16 g_wih[E3 * E_DIM];
__device__ __align__(16) __nv_bfloat16 g_wil[E3 * E_DIM];
__device__ __align__(16) __nv_bfloat16 g_woh[E_DIM * E_DIM];
__device__ __align__(16) __nv_bfloat16 g_wol[E_DIM * E_DIM];
__device__ __align__(16) __nv_bfloat16 g_qkvh[L_SEQ * E3];
__device__ __align__(16) __nv_bfloat16 g_qkvl[L_SEQ * E3];
__device__ __align__(16) __nv_bfloat16 g_ch[L_SEQ * E_DIM];
__device__ __align__(16) __nv_bfloat16 g_cl[L_SEQ * E_DIM];

__device__ __forceinline__ uint32_t smem_u32(const void* p) {
    uint32_t a;
    asm("{ .reg .u64 t; cvta.to.shared.u64 t, %1; cvt.u32.u64 %0, t; }" : "=r"(a) : "l"(p));
    return a;
}
__device__ __forceinline__ void cp_async16(uint32_t dst, const void* src) {
    asm volatile("cp.async.cg.shared.global [%0], [%1], 16;" :: "r"(dst), "l"(src));
}
__device__ __forceinline__ void cp_commit() {
    asm volatile("cp.async.commit_group;" ::: "memory");
}
__device__ __forceinline__ void cp_wait2() {
    asm volatile("cp.async.wait_group 2;" ::: "memory");
}
__device__ __forceinline__ void cp_wait1() {
    asm volatile("cp.async.wait_group 1;" ::: "memory");
}
__device__ __forceinline__ void cp_wait0() {
    asm volatile("cp.async.wait_group 0;" ::: "memory");
}
__device__ __forceinline__ void ldm_x4(uint32_t* r, uint32_t addr) {
    asm volatile("ldmatrix.sync.aligned.m8n8.x4.shared.b16 {%0,%1,%2,%3}, [%4];"
                 : "=r"(r[0]), "=r"(r[1]), "=r"(r[2]), "=r"(r[3]) : "r"(addr));
}
__device__ __forceinline__ void ldm_x4_t(uint32_t* r, uint32_t addr) {
    asm volatile("ldmatrix.sync.aligned.m8n8.x4.trans.shared.b16 {%0,%1,%2,%3}, [%4];"
                 : "=r"(r[0]), "=r"(r[1]), "=r"(r[2]), "=r"(r[3]) : "r"(addr));
}
__device__ __forceinline__ void mma_bf16(float* c, const uint32_t* a, const uint32_t* b) {
    asm volatile(
        "mma.sync.aligned.m16n8k16.row.col.f32.bf16.bf16.f32 "
        "{%0,%1,%2,%3}, {%4,%5,%6,%7}, {%8,%9}, {%0,%1,%2,%3};"
        : "+f"(c[0]), "+f"(c[1]), "+f"(c[2]), "+f"(c[3])
        : "r"(a[0]), "r"(a[1]), "r"(a[2]), "r"(a[3]), "r"(b[0]), "r"(b[1]));
}
__device__ __forceinline__ uint32_t pack_bf2(__nv_bfloat16 a, __nv_bfloat16 b) {
    __nv_bfloat162 t(a, b);
    return *reinterpret_cast<uint32_t*>(&t);
}
// exp2 polynomial (degree-6, rel err <= ~3e-5), FMA-pipe only
__device__ __forceinline__ float exp2p(float t) {
    t = fmaxf(t, -126.f);
    float fl = floorf(t);
    float f = t - fl;
    float p = 1.5403530e-4f;
    p = fmaf(p, f, 1.3333558e-3f);
    p = fmaf(p, f, 9.6181291e-3f);
    p = fmaf(p, f, 5.5504109e-2f);
    p = fmaf(p, f, 2.4022651e-1f);
    p = fmaf(p, f, 6.9314718e-1f);
    p = fmaf(p, f, 1.0f);
    return p * __int_as_float(((int)fl + 127) << 23);
}

// ---------------------------------------------------------------------------
// fp32 -> split bf16 (hi + lo)
// ---------------------------------------------------------------------------
__global__ void split_bf16_kernel(const float* __restrict__ in,
                                  __nv_bfloat16* __restrict__ hi,
                                  __nv_bfloat16* __restrict__ lo, int n4)
{
    int i = blockIdx.x * blockDim.x + threadIdx.x;
    if (i >= n4) return;
    float4 v = ((const float4*)in)[i];
    __nv_bfloat16 hx = __float2bfloat16(v.x);
    __nv_bfloat16 hy = __float2bfloat16(v.y);
    __nv_bfloat16 hz = __float2bfloat16(v.z);
    __nv_bfloat16 hw = __float2bfloat16(v.w);
    __nv_bfloat16 lx = __float2bfloat16(v.x - __bfloat162float(hx));
    __nv_bfloat16 ly = __float2bfloat16(v.y - __bfloat162float(hy));
    __nv_bfloat16 lz = __float2bfloat16(v.z - __bfloat162float(hz));
    __nv_bfloat16 lw = __float2bfloat16(v.w - __bfloat162float(hw));
    ((__nv_bfloat162*)hi)[2 * i]     = __nv_bfloat162(hx, hy);
    ((__nv_bfloat162*)hi)[2 * i + 1] = __nv_bfloat162(hz, hw);
    ((__nv_bfloat162*)lo)[2 * i]     = __nv_bfloat162(lx, ly);
    ((__nv_bfloat162*)lo)[2 * i + 1] = __nv_bfloat162(lz, lw);
}

// ---------------------------------------------------------------------------
// Split-bf16 mma.sync GEMM: C = A @ B^T + bias.
// 4-stage cp.async circular pipeline; one __syncthreads per stage;
// issue stage s+3 before computing stage s.
// ---------------------------------------------------------------------------
#define GM_TILE_BYTES 8192
#define GM_STAGE (4 * GM_TILE_BYTES)       // 32 KB per stage
#define GM_NSTAGE 4
#define GM_SMEM (GM_NSTAGE * GM_STAGE)     // 128 KB

__device__ __forceinline__ void issue_tile(uint32_t smem_tile,
                                           const __nv_bfloat16* __restrict__ G,
                                           int row0, int k0, int K, int tid)
{
#pragma unroll
    for (int t = 0; t < 2; t++) {
        int id = tid + t * 256;
        int r  = id >> 2;
        int c  = id & 3;
        int pc = c ^ ((r >> 1) & 3);
        cp_async16(smem_tile + r * 64 + pc * 16,
                   G + (size_t)(row0 + r) * K + k0 + c * 8);
    }
}
__device__ __forceinline__ void issue_stage(uint32_t base,
                                            const __nv_bfloat16* Ah, const __nv_bfloat16* Al,
                                            const __nv_bfloat16* Bh, const __nv_bfloat16* Bl,
                                            int m0, int n0, int k0, int K, int tid)
{
    issue_tile(base + 0 * GM_TILE_BYTES, Ah, m0, k0, K, tid);
    issue_tile(base + 1 * GM_TILE_BYTES, Al, m0, k0, K, tid);
    issue_tile(base + 2 * GM_TILE_BYTES, Bh, n0, k0, K, tid);
    issue_tile(base + 3 * GM_TILE_BYTES, Bl, n0, k0, K, tid);
}

__global__ __launch_bounds__(256, 1) void gemm_mma(
    const __nv_bfloat16* __restrict__ Ah, const __nv_bfloat16* __restrict__ Al,
    const __nv_bfloat16* __restrict__ Bh, const __nv_bfloat16* __restrict__ Bl,
    const float* __restrict__ bias, float* __restrict__ Cf,
    __nv_bfloat16* __restrict__ Ch, __nv_bfloat16* __restrict__ Cl,
    int M, int N, int K)
{
    extern __shared__ char smc[];
    const uint32_t sb = smem_u32(smc);
    const int tid = threadIdx.x;
    const int lane = tid & 31;
    const int wid = tid >> 5;
    const int wm = wid & 1;
    const int wn = wid >> 1;
    const int m0 = blockIdx.y * 128;
    const int n0 = blockIdx.x * 128;

    const int S = K >> 5;

    // prologue: stages 0..2
#pragma unroll
    for (int s = 0; s < 3; s++) {
        issue_stage(sb + s * GM_STAGE, Ah, Al, Bh, Bl, m0, n0, s * 32, K, tid);
        cp_commit();
    }

    float acc[4][4][4];
#pragma unroll
    for (int i = 0; i < 4; i++)
#pragma unroll
        for (int j = 0; j < 4; j++)
#pragma unroll
            for (int r = 0; r < 4; r++) acc[i][j][r] = 0.f;

    const int a_r = wm * 64 + (lane & 15);
    const int a_c = (lane >> 4);
    const int b_sub = lane >> 3;
    const int b_r = wn * 32 + (lane & 7) + (b_sub >> 1) * 8;
    const int b_c = (b_sub & 1);

    for (int s = 0; s < S; s++) {
        cp_wait2();               // stage s resident; s+1, s+2 in flight
        __syncthreads();          // all warps done with stage s-1 (frees buffer (s+3)&3)

        // issue stage s+3 into the freed buffer, BEFORE compute
        if (s + 3 < S)
            issue_stage(sb + ((s + 3) & 3) * GM_STAGE, Ah, Al, Bh, Bl,
                        m0, n0, (s + 3) * 32, K, tid);
        cp_commit();              // unconditional: uniform group counting through drain

        const uint32_t base = sb + (s & 3) * GM_STAGE;
        const uint32_t tAh = base;
        const uint32_t tAl = base + GM_TILE_BYTES;
        const uint32_t tBh = base + 2 * GM_TILE_BYTES;
        const uint32_t tBl = base + 3 * GM_TILE_BYTES;

#pragma unroll
        for (int ks = 0; ks < 2; ks++) {
            uint32_t ah[4][4], al[4][4], bh[4][2], bl[4][2];
#pragma unroll
            for (int mt = 0; mt < 4; mt++) {
                int r = a_r + mt * 16;
                int pc = (ks * 2 + a_c) ^ ((r >> 1) & 3);
                uint32_t off = r * 64 + pc * 16;
                ldm_x4(ah[mt], tAh + off);
                ldm_x4(al[mt], tAl + off);
            }
#pragma unroll
            for (int g = 0; g < 2; g++) {
                int r = b_r + g * 16;
                int pc = (ks * 2 + b_c) ^ ((r >> 1) & 3);
                uint32_t off = r * 64 + pc * 16;
                uint32_t th[4], tl[4];
                ldm_x4(th, tBh + off);
                ldm_x4(tl, tBl + off);
                bh[g * 2][0] = th[0]; bh[g * 2][1] = th[1];
                bh[g * 2 + 1][0] = th[2]; bh[g * 2 + 1][1] = th[3];
                bl[g * 2][0] = tl[0]; bl[g * 2][1] = tl[1];
                bl[g * 2 + 1][0] = tl[2]; bl[g * 2 + 1][1] = tl[3];
            }
#pragma unroll
            for (int mt = 0; mt < 4; mt++)
#pragma unroll
                for (int nt = 0; nt < 4; nt++) {
                    mma_bf16(acc[mt][nt], ah[mt], bh[nt]);
                    mma_bf16(acc[mt][nt], al[mt], bh[nt]);
                    mma_bf16(acc[mt][nt], ah[mt], bl[nt]);
                }
        }
    }

    const int cm = m0 + wm * 64 + (lane >> 2);
    const int cn = n0 + wn * 32 + (lane & 3) * 2;
    if (Cf) {
#pragma unroll
        for (int nt = 0; nt < 4; nt++) {
            float b0 = bias[cn + nt * 8];
            float b1 = bias[cn + nt * 8 + 1];
#pragma unroll
            for (int mt = 0; mt < 4; mt++) {
                float* r0 = Cf + (size_t)(cm + mt * 16) * N + cn + nt * 8;
                float* r1 = r0 + 8 * N;
                *(float2*)r0 = make_float2(acc[mt][nt][0] + b0, acc[mt][nt][1] + b1);
                *(float2*)r1 = make_float2(acc[mt][nt][2] + b0, acc[mt][nt][3] + b1);
            }
        }
    } else {
#pragma unroll
        for (int nt = 0; nt < 4; nt++) {
            float b0 = bias[cn + nt * 8];
            float b1 = bias[cn + nt * 8 + 1];
#pragma unroll
            for (int mt = 0; mt < 4; mt++) {
#pragma unroll
                for (int half = 0; half < 2; half++) {
                    float v0 = acc[mt][nt][2 * half + 0] + b0;
                    float v1 = acc[mt][nt][2 * half + 1] + b1;
                    __nv_bfloat16 h0 = __float2bfloat16(v0);
                    __nv_bfloat16 h1 = __float2bfloat16(v1);
                    __nv_bfloat16 l0 = __float2bfloat16(v0 - __bfloat162float(h0));
                    __nv_bfloat16 l1 = __float2bfloat16(v1 - __bfloat162float(h1));
                    size_t off = (size_t)(cm + mt * 16 + half * 8) * N + cn + nt * 8;
                    *(uint32_t*)(Ch + off) = pack_bf2(h0, h1);
                    *(uint32_t*)(Cl + off) = pack_bf2(l0, l1);
                }
            }
        }
    }
}

// ---------------------------------------------------------------------------
// Tensor-core flash attention (unchanged from R4 passing kernel)
// ---------------------------------------------------------------------------
#define ATT_STAGE 65536
#define ATT_SMEM (2 * ATT_STAGE)
#define ATT_NT 32

__device__ __forceinline__ uint32_t sw_addr(uint32_t base, int r, int c) {
    return base + r * 256 + ((c ^ (r & 7)) << 4);
}
__device__ __forceinline__ void att_load_tile(uint32_t dst,
                                              const __nv_bfloat16* __restrict__ g,
                                              int k0, int tid)
{
#pragma unroll
    for (int i = 0; i < 4; i++) {
        int id = tid + i * 256;
        int r = id >> 4;
        int c = id & 15;
        cp_async16(sw_addr(dst, r, c), g + (size_t)(k0 + r) * E3 + c * 8);
    }
}

__global__ __launch_bounds__(256, 1) void attn_tc(
    const __nv_bfloat16* __restrict__ qkvh, const __nv_bfloat16* __restrict__ qkvl,
    const float* __restrict__ biasM,
    __nv_bfloat16* __restrict__ ch, __nv_bfloat16* __restrict__ cl)
{
    extern __shared__ char smc[];
    const uint32_t sb = smem_u32(smc);
    const int tid = threadIdx.x;
    const int lane = tid & 31;
    const int wid = tid >> 5;
    const int h = blockIdx.y;
    const int q0 = blockIdx.x * 128;

    const uint32_t buf0 = sb;
    const uint32_t buf1 = sb + ATT_STAGE;

    const __nv_bfloat16* gKh = qkvh + E_DIM + h * D_HEAD;
    const __nv_bfloat16* gKl = qkvl + E_DIM + h * D_HEAD;
    const __nv_bfloat16* gVh = qkvh + 2 * E_DIM + h * D_HEAD;
    const __nv_bfloat16* gVl = qkvl + 2 * E_DIM + h * D_HEAD;

    {
        const __nv_bfloat16* gqh = qkvh + (size_t)q0 * E3 + h * D_HEAD;
        const __nv_bfloat16* gql = qkvl + (size_t)q0 * E3 + h * D_HEAD;
#pragma unroll
        for (int i = 0; i < 8; i++) {
            int id = tid + i * 256;
            int r = id >> 4;
            int c = id & 15;
            cp_async16(sw_addr(buf0, r, c), gqh + (size_t)r * E3 + c * 8);
        }
#pragma unroll
        for (int i = 0; i < 8; i++) {
            int id = tid + i * 256;
            int r = id >> 4;
            int c = id & 15;
            cp_async16(sw_addr(buf0 + 32768, r, c), gql + (size_t)r * E3 + c * 8);
        }
        cp_commit();
    }
    att_load_tile(buf1 + 0,     gKh, 0, tid);
    att_load_tile(buf1 + 16384, gKl, 0, tid);
    att_load_tile(buf1 + 32768, gVh, 0, tid);
    att_load_tile(buf1 + 49152, gVl, 0, tid);
    cp_commit();

    cp_wait1();
    __syncthreads();

    uint32_t qh_f[8][4], ql_f[8][4];
    {
        int r = wid * 16 + (lane & 15);
#pragma unroll
        for (int kf = 0; kf < 8; kf++) {
            int c = 2 * kf + (lane >> 4);
            ldm_x4(qh_f[kf], sw_addr(buf0, r, c));
            ldm_x4(ql_f[kf], sw_addr(buf0 + 32768, r, c));
        }
    }
    __syncthreads();

    att_load_tile(buf0 + 0,     gKh, 64, tid);
    att_load_tile(buf0 + 16384, gKl, 64, tid);
    att_load_tile(buf0 + 32768, gVh, 64, tid);
    att_load_tile(buf0 + 49152, gVl, 64, tid);
    cp_commit();

    float mA = -INFINITY, mB = -INFINITY, lA = 0.f, lB = 0.f;
    float ctx[16][4];
#pragma unroll
    for (int i = 0; i < 16; i++)
#pragma unroll
        for (int j = 0; j < 4; j++) ctx[i][j] = 0.f;

    const float SCALE = 0.088388347648318447f;
    const float LOG2E = 1.4426950408889634f;
    const int rA = q0 + wid * 16 + (lane >> 2);
    const int rB = rA + 8;
    const int cb = 2 * (lane & 3);

    const int s_br = (lane & 7) + ((lane >> 4) & 1) * 8;
    const int s_bc = (lane >> 3) & 1;
    const int a_r = (lane & 15);
    const int a_c = (lane >> 4);

    for (int kt = 0; kt < ATT_NT; kt++) {
        if (kt < ATT_NT - 2) cp_wait1(); else cp_wait0();
        __syncthreads();
        const uint32_t buf = (kt & 1) ? buf0 : buf1;
        const int k0 = kt * 64;

        float sacc[8][4];
#pragma unroll
        for (int i = 0; i < 8; i++)
#pragma unroll
            for (int j = 0; j < 4; j++) sacc[i][j] = 0.f;

#pragma unroll
        for (int kf = 0; kf < 8; kf++) {
#pragma unroll
            for (int ng = 0; ng < 4; ng++) {
                int r = ng * 16 + s_br;
                int c = 2 * kf + s_bc;
                uint32_t th[4], tl[4];
                ldm_x4(th, sw_addr(buf + 0, r, c));
                ldm_x4(tl, sw_addr(buf + 16384, r, c));
                uint32_t bh0[2] = {th[0], th[1]}, bh1[2] = {th[2], th[3]};
                uint32_t bl0[2] = {tl[0], tl[1]}, bl1[2] = {tl[2], tl[3]};
                mma_bf16(sacc[2 * ng],     qh_f[kf], bh0);
                mma_bf16(sacc[2 * ng],     ql_f[kf], bh0);
                mma_bf16(sacc[2 * ng],     qh_f[kf], bl0);
                mma_bf16(sacc[2 * ng + 1], qh_f[kf], bh1);
                mma_bf16(sacc[2 * ng + 1], ql_f[kf], bh1);
                mma_bf16(sacc[2 * ng + 1], qh_f[kf], bl1);
            }
        }

        float mxA = -INFINITY, mxB = -INFINITY;
#pragma unroll
        for (int nt = 0; nt < 8; nt++) {
            float2 bA = *(const float2*)(biasM + (size_t)rA * L_SEQ + k0 + nt * 8 + cb);
            float2 bB = *(const float2*)(biasM + (size_t)rB * L_SEQ + k0 + nt * 8 + cb);
            sacc[nt][0] = fmaf(sacc[nt][0], SCALE, bA.x);
            sacc[nt][1] = fmaf(sacc[nt][1], SCALE, bA.y);
            sacc[nt][2] = fmaf(sacc[nt][2], SCALE, bB.x);
            sacc[nt][3] = fmaf(sacc[nt][3], SCALE, bB.y);
            mxA = fmaxf(mxA, fmaxf(sacc[nt][0], sacc[nt][1]));
            mxB = fmaxf(mxB, fmaxf(sacc[nt][2], sacc[nt][3]));
        }
        mxA = fmaxf(mxA, __shfl_xor_sync(0xffffffffu, mxA, 1));
        mxA = fmaxf(mxA, __shfl_xor_sync(0xffffffffu, mxA, 2));
        mxB = fmaxf(mxB, __shfl_xor_sync(0xffffffffu, mxB, 1));
        mxB = fmaxf(mxB, __shfl_xor_sync(0xffffffffu, mxB, 2));
        float mnA = fmaxf(mA, mxA), mnB = fmaxf(mB, mxB);
        float alA = exp2p((mA - mnA) * LOG2E);
        float alB = exp2p((mB - mnB) * LOG2E);
        float negA = mnA * LOG2E, negB = mnB * LOG2E;
        float sumA = 0.f, sumB = 0.f;
#pragma unroll
        for (int nt = 0; nt < 8; nt++) {
            sacc[nt][0] = exp2p(fmaf(sacc[nt][0], LOG2E, -negA));
            sacc[nt][1] = exp2p(fmaf(sacc[nt][1], LOG2E, -negA));
            sacc[nt][2] = exp2p(fmaf(sacc[nt][2], LOG2E, -negB));
            sacc[nt][3] = exp2p(fmaf(sacc[nt][3], LOG2E, -negB));
            sumA += sacc[nt][0] + sacc[nt][1];
            sumB += sacc[nt][2] + sacc[nt][3];
        }
        sumA += __shfl_xor_sync(0xffffffffu, sumA, 1);
        sumA += __shfl_xor_sync(0xffffffffu, sumA, 2);
        sumB += __shfl_xor_sync(0xffffffffu, sumB, 1);
        sumB += __shfl_xor_sync(0xffffffffu, sumB, 2);
        lA = lA * alA + sumA;
        lB = lB * alB + sumB;
        mA = mnA; mB = mnB;
#pragma unroll
        for (int nt = 0; nt < 16; nt++) {
            ctx[nt][0] *= alA; ctx[nt][1] *= alA;
            ctx[nt][2] *= alB; ctx[nt][3] *= alB;
        }

        uint32_t pah[4][4], pal[4][4];
#pragma unroll
        for (int kb = 0; kb < 4; kb++) {
#pragma unroll
            for (int half = 0; half < 2; half++) {
#pragma unroll
                for (int sub = 0; sub < 2; sub++) {
                    float p0 = sacc[2 * kb + sub][2 * half + 0];
                    float p1 = sacc[2 * kb + sub][2 * half + 1];
                    __nv_bfloat16 h0 = __float2bfloat16(p0);
                    __nv_bfloat16 h1 = __float2bfloat16(p1);
                    __nv_bfloat16 l0 = __float2bfloat16(p0 - __bfloat162float(h0));
                    __nv_bfloat16 l1 = __float2bfloat16(p1 - __bfloat162float(h1));
                    pah[kb][sub * 2 + half] = pack_bf2(h0, h1);
                    pal[kb][sub * 2 + half] = pack_bf2(l0, l1);
                }
            }
        }

#pragma unroll
        for (int kb = 0; kb < 4; kb++) {
#pragma unroll
            for (int db = 0; db < 8; db++) {
                int r = kb * 16 + a_r;
                int c = 2 * db + a_c;
                uint32_t th[4], tl[4];
                ldm_x4_t(th, sw_addr(buf + 32768, r, c));
                ldm_x4_t(tl, sw_addr(buf + 49152, r, c));
                uint32_t bh0[2] = {th[0], th[1]}, bh1[2] = {th[2], th[3]};
                uint32_t bl0[2] = {tl[0], tl[1]}, bl1[2] = {tl[2], tl[3]};
                mma_bf16(ctx[2 * db],     pah[kb], bh0);
                mma_bf16(ctx[2 * db],     pal[kb], bh0);
                mma_bf16(ctx[2 * db],     pah[kb], bl0);
                mma_bf16(ctx[2 * db + 1], pah[kb], bh1);
                mma_bf16(ctx[2 * db + 1], pal[kb], bh1);
                mma_bf16(ctx[2 * db + 1], pah[kb], bl1);
            }
        }

        __syncthreads();
        if (kt + 2 < ATT_NT) {
            const uint32_t nbuf = (kt & 1) ? buf0 : buf1;
            const int nk0 = (kt + 2) * 64;
            att_load_tile(nbuf + 0,     gKh, nk0, tid);
            att_load_tile(nbuf + 16384, gKl, nk0, tid);
            att_load_tile(nbuf + 32768, gVh, nk0, tid);
            att_load_tile(nbuf + 49152, gVl, nk0, tid);
            cp_commit();
        }
    }

    float iA = 1.f / lA, iB = 1.f / lB;
#pragma unroll
    for (int nt = 0; nt < 16; nt++) {
        int col = h * D_HEAD + nt * 8 + cb;
        float v0 = ctx[nt][0] * iA, v1 = ctx[nt][1] * iA;
        float v2 = ctx[nt][2] * iB, v3 = ctx[nt][3] * iB;
        __nv_bfloat16 h0 = __float2bfloat16(v0), h1 = __float2bfloat16(v1);
        __nv_bfloat16 h2 = __float2bfloat16(v2), h3 = __float2bfloat16(v3);
        __nv_bfloat16 l0 = __float2bfloat16(v0 - __bfloat162float(h0));
        __nv_bfloat16 l1 = __float2bfloat16(v1 - __bfloat162float(h1));
        __nv_bfloat16 l2 = __float2bfloat16(v2 - __bfloat162float(h2));
        __nv_bfloat16 l3 = __float2bfloat16(v3 - __bfloat162float(h3));
        *(uint32_t*)(ch + (size_t)rA * E_DIM + col) = pack_bf2(h0, h1);
        *(uint32_t*)(cl + (size_t)rA * E_DIM + col) = pack_bf2(l0, l1);
        *(uint32_t*)(ch + (size_t)rB * E_DIM + col) = pack_bf2(h2, h3);
        *(uint32_t*)(cl + (size_t)rB * E_DIM + col) = pack_bf2(l2, l3);
    }
}

// ---------------------------------------------------------------------------
extern "C" void kernel_launch(void* const* d_in, const int* in_sizes, int n_in,
                              void* d_out, int out_size)
{
    const float* x     = (const float*)d_in[0];
    const float* biasM = (const float*)d_in[1];
    const float* w_in  = (const float*)d_in[2];
    const float* b_in  = (const float*)d_in[3];
    const float* w_out = (const float*)d_in[4];
    const float* b_out = (const float*)d_in[5];
    float* out = (float*)d_out;

    __nv_bfloat16 *xh, *xl, *wih, *wil, *woh, *wol, *qkvh, *qkvl, *ch, *cl;
    cudaGetSymbolAddress((void**)&xh, g_xh);
    cudaGetSymbolAddress((void**)&xl, g_xl);
    cudaGetSymbolAddress((void**)&wih, g_wih);
    cudaGetSymbolAddress((void**)&wil, g_wil);
    cudaGetSymbolAddress((void**)&woh, g_woh);
    cudaGetSymbolAddress((void**)&wol, g_wol);
    cudaGetSymbolAddress((void**)&qkvh, g_qkvh);
    cudaGetSymbolAddress((void**)&qkvl, g_qkvl);
    cudaGetSymbolAddress((void**)&ch, g_ch);
    cudaGetSymbolAddress((void**)&cl, g_cl);

    cudaFuncSetAttribute(gemm_mma, cudaFuncAttributeMaxDynamicSharedMemorySize, GM_SMEM);
    cudaFuncSetAttribute(attn_tc, cudaFuncAttributeMaxDynamicSharedMemorySize, ATT_SMEM);

    {
        int n4 = (L_SEQ * E_DIM) / 4;
        split_bf16_kernel<<<(n4 + 255) / 256, 256>>>(x, xh, xl, n4);
        int w4 = (E3 * E_DIM) / 4;
        split_bf16_kernel<<<(w4 + 255) / 256, 256>>>(w_in, wih, wil, w4);
        int o4 = (E_DIM * E_DIM) / 4;
        split_bf16_kernel<<<(o4 + 255) / 256, 256>>>(w_out, woh, wol, o4);
    }

    // 1) QKV projection -> split bf16 output
    gemm_mma<<<dim3(E3 / 128, L_SEQ / 128), 256, GM_SMEM>>>(
        xh, xl, wih, wil, b_in, nullptr, qkvh, qkvl, L_SEQ, E3, E_DIM);

    // 2) Tensor-core attention -> split bf16 ctx
    attn_tc<<<dim3(L_SEQ / 128, H_NUM), 256, ATT_SMEM>>>(
        qkvh, qkvl, biasM, ch, cl);

    // 3) out projection -> fp32 output
    gemm_mma<<<dim3(E_DIM / 128, L_SEQ / 128), 256, GM_SMEM>>>(
        ch, cl, woh, wol, b_out, out, nullptr, nullptr, L_SEQ, E_DIM, E_DIM);
}

// round 6
// speedup vs baseline: 2.7161x; 1.0015x over previous
#include <cuda_runtime.h>
#include <cuda_bf16.h>
#include <cstdint>
#include <math.h>

#define L_SEQ 2048
#define E_DIM 2048
#define H_NUM 16
#define D_HEAD 128
#define E3 6144

// ---------------------------------------------------------------------------
// Device-global scratch (allocation-free rule)
// ---------------------------------------------------------------------------
__device__ __align__(16) __nv_bfloat16 g_xh[L_SEQ * E_DIM];
__device__ __align__(16) __nv_bfloat16 g_xl[L_SEQ * E_DIM];
__device__ __align__(16) __nv_bfloat16 g_wih[E3 * E_DIM];
__device__ __align__(16) __nv_bfloat16 g_wil[E3 * E_DIM];
__device__ __align__(16) __nv_bfloat16 g_woh[E_DIM * E_DIM];
__device__ __align__(16) __nv_bfloat16 g_wol[E_DIM * E_DIM];
__device__ __align__(16) __nv_bfloat16 g_qkvh[L_SEQ * E3];
__device__ __align__(16) __nv_bfloat16 g_qkvl[L_SEQ * E3];
__device__ __align__(16) __nv_bfloat16 g_ch[L_SEQ * E_DIM];
__device__ __align__(16) __nv_bfloat16 g_cl[L_SEQ * E_DIM];

__device__ __forceinline__ uint32_t smem_u32(const void* p) {
    uint32_t a;
    asm("{ .reg .u64 t; cvta.to.shared.u64 t, %1; cvt.u32.u64 %0, t; }" : "=r"(a) : "l"(p));
    return a;
}
__device__ __forceinline__ void cp_async16(uint32_t dst, const void* src) {
    asm volatile("cp.async.cg.shared.global [%0], [%1], 16;" :: "r"(dst), "l"(src));
}
__device__ __forceinline__ void cp_commit() {
    asm volatile("cp.async.commit_group;" ::: "memory");
}
__device__ __forceinline__ void cp_wait2() {
    asm volatile("cp.async.wait_group 2;" ::: "memory");
}
__device__ __forceinline__ void cp_wait1() {
    asm volatile("cp.async.wait_group 1;" ::: "memory");
}
__device__ __forceinline__ void cp_wait0() {
    asm volatile("cp.async.wait_group 0;" ::: "memory");
}
__device__ __forceinline__ void ldm_x4(uint32_t* r, uint32_t addr) {
    asm volatile("ldmatrix.sync.aligned.m8n8.x4.shared.b16 {%0,%1,%2,%3}, [%4];"
                 : "=r"(r[0]), "=r"(r[1]), "=r"(r[2]), "=r"(r[3]) : "r"(addr));
}
__device__ __forceinline__ void ldm_x4_t(uint32_t* r, uint32_t addr) {
    asm volatile("ldmatrix.sync.aligned.m8n8.x4.trans.shared.b16 {%0,%1,%2,%3}, [%4];"
                 : "=r"(r[0]), "=r"(r[1]), "=r"(r[2]), "=r"(r[3]) : "r"(addr));
}
// NOTE: non-volatile — pure register op; lets ptxas interleave dependent chains
__device__ __forceinline__ void mma_bf16(float* c, const uint32_t* a, const uint32_t* b) {
    asm("mma.sync.aligned.m16n8k16.row.col.f32.bf16.bf16.f32 "
        "{%0,%1,%2,%3}, {%4,%5,%6,%7}, {%8,%9}, {%0,%1,%2,%3};"
        : "+f"(c[0]), "+f"(c[1]), "+f"(c[2]), "+f"(c[3])
        : "r"(a[0]), "r"(a[1]), "r"(a[2]), "r"(a[3]), "r"(b[0]), "r"(b[1]));
}
__device__ __forceinline__ uint32_t pack_bf2(__nv_bfloat16 a, __nv_bfloat16 b) {
    __nv_bfloat162 t(a, b);
    return *reinterpret_cast<uint32_t*>(&t);
}
// exp2 polynomial (degree-6, rel err <= ~3e-5), FMA-pipe only
__device__ __forceinline__ float exp2p(float t) {
    t = fmaxf(t, -126.f);
    float fl = floorf(t);
    float f = t - fl;
    float p = 1.5403530e-4f;
    p = fmaf(p, f, 1.3333558e-3f);
    p = fmaf(p, f, 9.6181291e-3f);
    p = fmaf(p, f, 5.5504109e-2f);
    p = fmaf(p, f, 2.4022651e-1f);
    p = fmaf(p, f, 6.9314718e-1f);
    p = fmaf(p, f, 1.0f);
    return p * __int_as_float(((int)fl + 127) << 23);
}

// ---------------------------------------------------------------------------
// fp32 -> split bf16 (hi + lo)
// ---------------------------------------------------------------------------
__global__ void split_bf16_kernel(const float* __restrict__ in,
                                  __nv_bfloat16* __restrict__ hi,
                                  __nv_bfloat16* __restrict__ lo, int n4)
{
    int i = blockIdx.x * blockDim.x + threadIdx.x;
    if (i >= n4) return;
    float4 v = ((const float4*)in)[i];
    __nv_bfloat16 hx = __float2bfloat16(v.x);
    __nv_bfloat16 hy = __float2bfloat16(v.y);
    __nv_bfloat16 hz = __float2bfloat16(v.z);
    __nv_bfloat16 hw = __float2bfloat16(v.w);
    __nv_bfloat16 lx = __float2bfloat16(v.x - __bfloat162float(hx));
    __nv_bfloat16 ly = __float2bfloat16(v.y - __bfloat162float(hy));
    __nv_bfloat16 lz = __float2bfloat16(v.z - __bfloat162float(hz));
    __nv_bfloat16 lw = __float2bfloat16(v.w - __bfloat162float(hw));
    ((__nv_bfloat162*)hi)[2 * i]     = __nv_bfloat162(hx, hy);
    ((__nv_bfloat162*)hi)[2 * i + 1] = __nv_bfloat162(hz, hw);
    ((__nv_bfloat162*)lo)[2 * i]     = __nv_bfloat162(lx, ly);
    ((__nv_bfloat162*)lo)[2 * i + 1] = __nv_bfloat162(lz, lw);
}

// ---------------------------------------------------------------------------
// Split-bf16 mma.sync GEMM: C = A @ B^T + bias.
// 4-stage cp.async pipeline; 3-pass MMAs separated per pass (dep distance 16).
// ---------------------------------------------------------------------------
#define GM_TILE_BYTES 8192
#define GM_STAGE (4 * GM_TILE_BYTES)
#define GM_NSTAGE 4
#define GM_SMEM (GM_NSTAGE * GM_STAGE)     // 128 KB

__device__ __forceinline__ void issue_tile(uint32_t smem_tile,
                                           const __nv_bfloat16* __restrict__ G,
                                           int row0, int k0, int K, int tid)
{
#pragma unroll
    for (int t = 0; t < 2; t++) {
        int id = tid + t * 256;
        int r  = id >> 2;
        int c  = id & 3;
        int pc = c ^ ((r >> 1) & 3);
        cp_async16(smem_tile + r * 64 + pc * 16,
                   G + (size_t)(row0 + r) * K + k0 + c * 8);
    }
}
__device__ __forceinline__ void issue_stage(uint32_t base,
                                            const __nv_bfloat16* Ah, const __nv_bfloat16* Al,
                                            const __nv_bfloat16* Bh, const __nv_bfloat16* Bl,
                                            int m0, int n0, int k0, int K, int tid)
{
    issue_tile(base + 0 * GM_TILE_BYTES, Ah, m0, k0, K, tid);
    issue_tile(base + 1 * GM_TILE_BYTES, Al, m0, k0, K, tid);
    issue_tile(base + 2 * GM_TILE_BYTES, Bh, n0, k0, K, tid);
    issue_tile(base + 3 * GM_TILE_BYTES, Bl, n0, k0, K, tid);
}

__global__ __launch_bounds__(256, 1) void gemm_mma(
    const __nv_bfloat16* __restrict__ Ah, const __nv_bfloat16* __restrict__ Al,
    const __nv_bfloat16* __restrict__ Bh, const __nv_bfloat16* __restrict__ Bl,
    const float* __restrict__ bias, float* __restrict__ Cf,
    __nv_bfloat16* __restrict__ Ch, __nv_bfloat16* __restrict__ Cl,
    int M, int N, int K)
{
    extern __shared__ char smc[];
    const uint32_t sb = smem_u32(smc);
    const int tid = threadIdx.x;
    const int lane = tid & 31;
    const int wid = tid >> 5;
    const int wm = wid & 1;
    const int wn = wid >> 1;
    const int m0 = blockIdx.y * 128;
    const int n0 = blockIdx.x * 128;

    const int S = K >> 5;

#pragma unroll
    for (int s = 0; s < 3; s++) {
        issue_stage(sb + s * GM_STAGE, Ah, Al, Bh, Bl, m0, n0, s * 32, K, tid);
        cp_commit();
    }

    float acc[4][4][4];
#pragma unroll
    for (int i = 0; i < 4; i++)
#pragma unroll
        for (int j = 0; j < 4; j++)
#pragma unroll
            for (int r = 0; r < 4; r++) acc[i][j][r] = 0.f;

    const int a_r = wm * 64 + (lane & 15);
    const int a_c = (lane >> 4);
    const int b_sub = lane >> 3;
    const int b_r = wn * 32 + (lane & 7) + (b_sub >> 1) * 8;
    const int b_c = (b_sub & 1);

    for (int s = 0; s < S; s++) {
        cp_wait2();
        __syncthreads();

        if (s + 3 < S)
            issue_stage(sb + ((s + 3) & 3) * GM_STAGE, Ah, Al, Bh, Bl,
                        m0, n0, (s + 3) * 32, K, tid);
        cp_commit();

        const uint32_t base = sb + (s & 3) * GM_STAGE;
        const uint32_t tAh = base;
        const uint32_t tAl = base + GM_TILE_BYTES;
        const uint32_t tBh = base + 2 * GM_TILE_BYTES;
        const uint32_t tBl = base + 3 * GM_TILE_BYTES;

#pragma unroll
        for (int ks = 0; ks < 2; ks++) {
            uint32_t ah[4][4], al[4][4], bh[4][2], bl[4][2];
#pragma unroll
            for (int mt = 0; mt < 4; mt++) {
                int r = a_r + mt * 16;
                int pc = (ks * 2 + a_c) ^ ((r >> 1) & 3);
                uint32_t off = r * 64 + pc * 16;
                ldm_x4(ah[mt], tAh + off);
                ldm_x4(al[mt], tAl + off);
            }
#pragma unroll
            for (int g = 0; g < 2; g++) {
                int r = b_r + g * 16;
                int pc = (ks * 2 + b_c) ^ ((r >> 1) & 3);
                uint32_t off = r * 64 + pc * 16;
                uint32_t th[4], tl[4];
                ldm_x4(th, tBh + off);
                ldm_x4(tl, tBl + off);
                bh[g * 2][0] = th[0]; bh[g * 2][1] = th[1];
                bh[g * 2 + 1][0] = th[2]; bh[g * 2 + 1][1] = th[3];
                bl[g * 2][0] = tl[0]; bl[g * 2][1] = tl[1];
                bl[g * 2 + 1][0] = tl[2]; bl[g * 2 + 1][1] = tl[3];
            }
            // 3 passes SEPARATED: dependency distance 16 per accumulator
#pragma unroll
            for (int mt = 0; mt < 4; mt++)
#pragma unroll
                for (int nt = 0; nt < 4; nt++)
                    mma_bf16(acc[mt][nt], ah[mt], bh[nt]);
#pragma unroll
            for (int mt = 0; mt < 4; mt++)
#pragma unroll
                for (int nt = 0; nt < 4; nt++)
                    mma_bf16(acc[mt][nt], al[mt], bh[nt]);
#pragma unroll
            for (int mt = 0; mt < 4; mt++)
#pragma unroll
                for (int nt = 0; nt < 4; nt++)
                    mma_bf16(acc[mt][nt], ah[mt], bl[nt]);
        }
    }

    const int cm = m0 + wm * 64 + (lane >> 2);
    const int cn = n0 + wn * 32 + (lane & 3) * 2;
    if (Cf) {
#pragma unroll
        for (int nt = 0; nt < 4; nt++) {
            float b0 = bias[cn + nt * 8];
            float b1 = bias[cn + nt * 8 + 1];
#pragma unroll
            for (int mt = 0; mt < 4; mt++) {
                float* r0 = Cf + (size_t)(cm + mt * 16) * N + cn + nt * 8;
                float* r1 = r0 + 8 * N;
                *(float2*)r0 = make_float2(acc[mt][nt][0] + b0, acc[mt][nt][1] + b1);
                *(float2*)r1 = make_float2(acc[mt][nt][2] + b0, acc[mt][nt][3] + b1);
            }
        }
    } else {
#pragma unroll
        for (int nt = 0; nt < 4; nt++) {
            float b0 = bias[cn + nt * 8];
            float b1 = bias[cn + nt * 8 + 1];
#pragma unroll
            for (int mt = 0; mt < 4; mt++) {
#pragma unroll
                for (int half = 0; half < 2; half++) {
                    float v0 = acc[mt][nt][2 * half + 0] + b0;
                    float v1 = acc[mt][nt][2 * half + 1] + b1;
                    __nv_bfloat16 h0 = __float2bfloat16(v0);
                    __nv_bfloat16 h1 = __float2bfloat16(v1);
                    __nv_bfloat16 l0 = __float2bfloat16(v0 - __bfloat162float(h0));
                    __nv_bfloat16 l1 = __float2bfloat16(v1 - __bfloat162float(h1));
                    size_t off = (size_t)(cm + mt * 16 + half * 8) * N + cn + nt * 8;
                    *(uint32_t*)(Ch + off) = pack_bf2(h0, h1);
                    *(uint32_t*)(Cl + off) = pack_bf2(l0, l1);
                }
            }
        }
    }
}

// ---------------------------------------------------------------------------
// Tensor-core flash attention (same structure; MMA now non-volatile)
// ---------------------------------------------------------------------------
#define ATT_STAGE 65536
#define ATT_SMEM (2 * ATT_STAGE)
#define ATT_NT 32

__device__ __forceinline__ uint32_t sw_addr(uint32_t base, int r, int c) {
    return base + r * 256 + ((c ^ (r & 7)) << 4);
}
__device__ __forceinline__ void att_load_tile(uint32_t dst,
                                              const __nv_bfloat16* __restrict__ g,
                                              int k0, int tid)
{
#pragma unroll
    for (int i = 0; i < 4; i++) {
        int id = tid + i * 256;
        int r = id >> 4;
        int c = id & 15;
        cp_async16(sw_addr(dst, r, c), g + (size_t)(k0 + r) * E3 + c * 8);
    }
}

__global__ __launch_bounds__(256, 1) void attn_tc(
    const __nv_bfloat16* __restrict__ qkvh, const __nv_bfloat16* __restrict__ qkvl,
    const float* __restrict__ biasM,
    __nv_bfloat16* __restrict__ ch, __nv_bfloat16* __restrict__ cl)
{
    extern __shared__ char smc[];
    const uint32_t sb = smem_u32(smc);
    const int tid = threadIdx.x;
    const int lane = tid & 31;
    const int wid = tid >> 5;
    const int h = blockIdx.y;
    const int q0 = blockIdx.x * 128;

    const uint32_t buf0 = sb;
    const uint32_t buf1 = sb + ATT_STAGE;

    const __nv_bfloat16* gKh = qkvh + E_DIM + h * D_HEAD;
    const __nv_bfloat16* gKl = qkvl + E_DIM + h * D_HEAD;
    const __nv_bfloat16* gVh = qkvh + 2 * E_DIM + h * D_HEAD;
    const __nv_bfloat16* gVl = qkvl + 2 * E_DIM + h * D_HEAD;

    {
        const __nv_bfloat16* gqh = qkvh + (size_t)q0 * E3 + h * D_HEAD;
        const __nv_bfloat16* gql = qkvl + (size_t)q0 * E3 + h * D_HEAD;
#pragma unroll
        for (int i = 0; i < 8; i++) {
            int id = tid + i * 256;
            int r = id >> 4;
            int c = id & 15;
            cp_async16(sw_addr(buf0, r, c), gqh + (size_t)r * E3 + c * 8);
        }
#pragma unroll
        for (int i = 0; i < 8; i++) {
            int id = tid + i * 256;
            int r = id >> 4;
            int c = id & 15;
            cp_async16(sw_addr(buf0 + 32768, r, c), gql + (size_t)r * E3 + c * 8);
        }
        cp_commit();
    }
    att_load_tile(buf1 + 0,     gKh, 0, tid);
    att_load_tile(buf1 + 16384, gKl, 0, tid);
    att_load_tile(buf1 + 32768, gVh, 0, tid);
    att_load_tile(buf1 + 49152, gVl, 0, tid);
    cp_commit();

    cp_wait1();
    __syncthreads();

    uint32_t qh_f[8][4], ql_f[8][4];
    {
        int r = wid * 16 + (lane & 15);
#pragma unroll
        for (int kf = 0; kf < 8; kf++) {
            int c = 2 * kf + (lane >> 4);
            ldm_x4(qh_f[kf], sw_addr(buf0, r, c));
            ldm_x4(ql_f[kf], sw_addr(buf0 + 32768, r, c));
        }
    }
    __syncthreads();

    att_load_tile(buf0 + 0,     gKh, 64, tid);
    att_load_tile(buf0 + 16384, gKl, 64, tid);
    att_load_tile(buf0 + 32768, gVh, 64, tid);
    att_load_tile(buf0 + 49152, gVl, 64, tid);
    cp_commit();

    float mA = -INFINITY, mB = -INFINITY, lA = 0.f, lB = 0.f;
    float ctx[16][4];
#pragma unroll
    for (int i = 0; i < 16; i++)
#pragma unroll
        for (int j = 0; j < 4; j++) ctx[i][j] = 0.f;

    const float SCALE = 0.088388347648318447f;
    const float LOG2E = 1.4426950408889634f;
    const int rA = q0 + wid * 16 + (lane >> 2);
    const int rB = rA + 8;
    const int cb = 2 * (lane & 3);

    const int s_br = (lane & 7) + ((lane >> 4) & 1) * 8;
    const int s_bc = (lane >> 3) & 1;
    const int a_r = (lane & 15);
    const int a_c = (lane >> 4);

    for (int kt = 0; kt < ATT_NT; kt++) {
        if (kt < ATT_NT - 2) cp_wait1(); else cp_wait0();
        __syncthreads();
        const uint32_t buf = (kt & 1) ? buf0 : buf1;
        const int k0 = kt * 64;

        float sacc[8][4];
#pragma unroll
        for (int i = 0; i < 8; i++)
#pragma unroll
            for (int j = 0; j < 4; j++) sacc[i][j] = 0.f;

#pragma unroll
        for (int kf = 0; kf < 8; kf++) {
#pragma unroll
            for (int ng = 0; ng < 4; ng++) {
                int r = ng * 16 + s_br;
                int c = 2 * kf + s_bc;
                uint32_t th[4], tl[4];
                ldm_x4(th, sw_addr(buf + 0, r, c));
                ldm_x4(tl, sw_addr(buf + 16384, r, c));
                uint32_t bh0[2] = {th[0], th[1]}, bh1[2] = {th[2], th[3]};
                uint32_t bl0[2] = {tl[0], tl[1]}, bl1[2] = {tl[2], tl[3]};
                mma_bf16(sacc[2 * ng],     qh_f[kf], bh0);
                mma_bf16(sacc[2 * ng + 1], qh_f[kf], bh1);
                mma_bf16(sacc[2 * ng],     ql_f[kf], bh0);
                mma_bf16(sacc[2 * ng + 1], ql_f[kf], bh1);
                mma_bf16(sacc[2 * ng],     qh_f[kf], bl0);
                mma_bf16(sacc[2 * ng + 1], qh_f[kf], bl1);
            }
        }

        float mxA = -INFINITY, mxB = -INFINITY;
#pragma unroll
        for (int nt = 0; nt < 8; nt++) {
            float2 bA = *(const float2*)(biasM + (size_t)rA * L_SEQ + k0 + nt * 8 + cb);
            float2 bB = *(const float2*)(biasM + (size_t)rB * L_SEQ + k0 + nt * 8 + cb);
            sacc[nt][0] = fmaf(sacc[nt][0], SCALE, bA.x);
            sacc[nt][1] = fmaf(sacc[nt][1], SCALE, bA.y);
            sacc[nt][2] = fmaf(sacc[nt][2], SCALE, bB.x);
            sacc[nt][3] = fmaf(sacc[nt][3], SCALE, bB.y);
            mxA = fmaxf(mxA, fmaxf(sacc[nt][0], sacc[nt][1]));
            mxB = fmaxf(mxB, fmaxf(sacc[nt][2], sacc[nt][3]));
        }
        mxA = fmaxf(mxA, __shfl_xor_sync(0xffffffffu, mxA, 1));
        mxA = fmaxf(mxA, __shfl_xor_sync(0xffffffffu, mxA, 2));
        mxB = fmaxf(mxB, __shfl_xor_sync(0xffffffffu, mxB, 1));
        mxB = fmaxf(mxB, __shfl_xor_sync(0xffffffffu, mxB, 2));
        float mnA = fmaxf(mA, mxA), mnB = fmaxf(mB, mxB);
        float alA = exp2p((mA - mnA) * LOG2E);
        float alB = exp2p((mB - mnB) * LOG2E);
        float negA = mnA * LOG2E, negB = mnB * LOG2E;
        float sumA = 0.f, sumB = 0.f;
#pragma unroll
        for (int nt = 0; nt < 8; nt++) {
            sacc[nt][0] = exp2p(fmaf(sacc[nt][0], LOG2E, -negA));
            sacc[nt][1] = exp2p(fmaf(sacc[nt][1], LOG2E, -negA));
            sacc[nt][2] = exp2p(fmaf(sacc[nt][2], LOG2E, -negB));
            sacc[nt][3] = exp2p(fmaf(sacc[nt][3], LOG2E, -negB));
            sumA += sacc[nt][0] + sacc[nt][1];
            sumB += sacc[nt][2] + sacc[nt][3];
        }
        sumA += __shfl_xor_sync(0xffffffffu, sumA, 1);
        sumA += __shfl_xor_sync(0xffffffffu, sumA, 2);
        sumB += __shfl_xor_sync(0xffffffffu, sumB, 1);
        sumB += __shfl_xor_sync(0xffffffffu, sumB, 2);
        lA = lA * alA + sumA;
        lB = lB * alB + sumB;
        mA = mnA; mB = mnB;
#pragma unroll
        for (int nt = 0; nt < 16; nt++) {
            ctx[nt][0] *= alA; ctx[nt][1] *= alA;
            ctx[nt][2] *= alB; ctx[nt][3] *= alB;
        }

        uint32_t pah[4][4], pal[4][4];
#pragma unroll
        for (int kb = 0; kb < 4; kb++) {
#pragma unroll
            for (int half = 0; half < 2; half++) {
#pragma unroll
                for (int sub = 0; sub < 2; sub++) {
                    float p0 = sacc[2 * kb + sub][2 * half + 0];
                    float p1 = sacc[2 * kb + sub][2 * half + 1];
                    __nv_bfloat16 h0 = __float2bfloat16(p0);
                    __nv_bfloat16 h1 = __float2bfloat16(p1);
                    __nv_bfloat16 l0 = __float2bfloat16(p0 - __bfloat162float(h0));
                    __nv_bfloat16 l1 = __float2bfloat16(p1 - __bfloat162float(h1));
                    pah[kb][sub * 2 + half] = pack_bf2(h0, h1);
                    pal[kb][sub * 2 + half] = pack_bf2(l0, l1);
                }
            }
        }

#pragma unroll
        for (int kb = 0; kb < 4; kb++) {
#pragma unroll
            for (int db = 0; db < 8; db++) {
                int r = kb * 16 + a_r;
                int c = 2 * db + a_c;
                uint32_t th[4], tl[4];
                ldm_x4_t(th, sw_addr(buf + 32768, r, c));
                ldm_x4_t(tl, sw_addr(buf + 49152, r, c));
                uint32_t bh0[2] = {th[0], th[1]}, bh1[2] = {th[2], th[3]};
                uint32_t bl0[2] = {tl[0], tl[1]}, bl1[2] = {tl[2], tl[3]};
                mma_bf16(ctx[2 * db],     pah[kb], bh0);
                mma_bf16(ctx[2 * db + 1], pah[kb], bh1);
                mma_bf16(ctx[2 * db],     pal[kb], bh0);
                mma_bf16(ctx[2 * db + 1], pal[kb], bh1);
                mma_bf16(ctx[2 * db],     pah[kb], bl0);
                mma_bf16(ctx[2 * db + 1], pah[kb], bl1);
            }
        }

        __syncthreads();
        if (kt + 2 < ATT_NT) {
            const uint32_t nbuf = (kt & 1) ? buf0 : buf1;
            const int nk0 = (kt + 2) * 64;
            att_load_tile(nbuf + 0,     gKh, nk0, tid);
            att_load_tile(nbuf + 16384, gKl, nk0, tid);
            att_load_tile(nbuf + 32768, gVh, nk0, tid);
            att_load_tile(nbuf + 49152, gVl, nk0, tid);
            cp_commit();
        }
    }

    float iA = 1.f / lA, iB = 1.f / lB;
#pragma unroll
    for (int nt = 0; nt < 16; nt++) {
        int col = h * D_HEAD + nt * 8 + cb;
        float v0 = ctx[nt][0] * iA, v1 = ctx[nt][1] * iA;
        float v2 = ctx[nt][2] * iB, v3 = ctx[nt][3] * iB;
        __nv_bfloat16 h0 = __float2bfloat16(v0), h1 = __float2bfloat16(v1);
        __nv_bfloat16 h2 = __float2bfloat16(v2), h3 = __float2bfloat16(v3);
        __nv_bfloat16 l0 = __float2bfloat16(v0 - __bfloat162float(h0));
        __nv_bfloat16 l1 = __float2bfloat16(v1 - __bfloat162float(h1));
        __nv_bfloat16 l2 = __float2bfloat16(v2 - __bfloat162float(h2));
        __nv_bfloat16 l3 = __float2bfloat16(v3 - __bfloat162float(h3));
        *(uint32_t*)(ch + (size_t)rA * E_DIM + col) = pack_bf2(h0, h1);
        *(uint32_t*)(cl + (size_t)rA * E_DIM + col) = pack_bf2(l0, l1);
        *(uint32_t*)(ch + (size_t)rB * E_DIM + col) = pack_bf2(h2, h3);
        *(uint32_t*)(cl + (size_t)rB * E_DIM + col) = pack_bf2(l2, l3);
    }
}

// ---------------------------------------------------------------------------
extern "C" void kernel_launch(void* const* d_in, const int* in_sizes, int n_in,
                              void* d_out, int out_size)
{
    const float* x     = (const float*)d_in[0];
    const float* biasM = (const float*)d_in[1];
    const float* w_in  = (const float*)d_in[2];
    const float* b_in  = (const float*)d_in[3];
    const float* w_out = (const float*)d_in[4];
    const float* b_out = (const float*)d_in[5];
    float* out = (float*)d_out;

    __nv_bfloat16 *xh, *xl, *wih, *wil, *woh, *wol, *qkvh, *qkvl, *ch, *cl;
    cudaGetSymbolAddress((void**)&xh, g_xh);
    cudaGetSymbolAddress((void**)&xl, g_xl);
    cudaGetSymbolAddress((void**)&wih, g_wih);
    cudaGetSymbolAddress((void**)&wil, g_wil);
    cudaGetSymbolAddress((void**)&woh, g_woh);
    cudaGetSymbolAddress((void**)&wol, g_wol);
    cudaGetSymbolAddress((void**)&qkvh, g_qkvh);
    cudaGetSymbolAddress((void**)&qkvl, g_qkvl);
    cudaGetSymbolAddress((void**)&ch, g_ch);
    cudaGetSymbolAddress((void**)&cl, g_cl);

    cudaFuncSetAttribute(gemm_mma, cudaFuncAttributeMaxDynamicSharedMemorySize, GM_SMEM);
    cudaFuncSetAttribute(attn_tc, cudaFuncAttributeMaxDynamicSharedMemorySize, ATT_SMEM);

    {
        int n4 = (L_SEQ * E_DIM) / 4;
        split_bf16_kernel<<<(n4 + 255) / 256, 256>>>(x, xh, xl, n4);
        int w4 = (E3 * E_DIM) / 4;
        split_bf16_kernel<<<(w4 + 255) / 256, 256>>>(w_in, wih, wil, w4);
        int o4 = (E_DIM * E_DIM) / 4;
        split_bf16_kernel<<<(o4 + 255) / 256, 256>>>(w_out, woh, wol, o4);
    }

    // 1) QKV projection -> split bf16 output
    gemm_mma<<<dim3(E3 / 128, L_SEQ / 128), 256, GM_SMEM>>>(
        xh, xl, wih, wil, b_in, nullptr, qkvh, qkvl, L_SEQ, E3, E_DIM);

    // 2) Tensor-core attention -> split bf16 ctx
    attn_tc<<<dim3(L_SEQ / 128, H_NUM), 256, ATT_SMEM>>>(
        qkvh, qkvl, biasM, ch, cl);

    // 3) out projection -> fp32 output
    gemm_mma<<<dim3(E_DIM / 128, L_SEQ / 128), 256, GM_SMEM>>>(
        ch, cl, woh, wol, b_out, out, nullptr, nullptr, L_SEQ, E_DIM, E_DIM);
}

// round 7
// speedup vs baseline: 2.8859x; 1.0625x over previous
#include <cuda_runtime.h>
#include <cuda_bf16.h>
#include <cstdint>
#include <math.h>

#define L_SEQ 2048
#define E_DIM 2048
#define H_NUM 16
#define D_HEAD 128
#define E3 6144

// ---------------------------------------------------------------------------
// Device-global scratch (allocation-free rule)
// ---------------------------------------------------------------------------
__device__ __align__(16) __nv_bfloat16 g_xh[L_SEQ * E_DIM];
__device__ __align__(16) __nv_bfloat16 g_xl[L_SEQ * E_DIM];
__device__ __align__(16) __nv_bfloat16 g_wih[E3 * E_DIM];
__device__ __align__(16) __nv_bfloat16 g_wil[E3 * E_DIM];
__device__ __align__(16) __nv_bfloat16 g_woh[E_DIM * E_DIM];
__device__ __align__(16) __nv_bfloat16 g_wol[E_DIM * E_DIM];
__device__ __align__(16) __nv_bfloat16 g_qkvh[L_SEQ * E3];
__device__ __align__(16) __nv_bfloat16 g_qkvl[L_SEQ * E3];
__device__ __align__(16) __nv_bfloat16 g_ch[L_SEQ * E_DIM];
__device__ __align__(16) __nv_bfloat16 g_cl[L_SEQ * E_DIM];

__device__ __forceinline__ uint32_t smem_u32(const void* p) {
    uint32_t a;
    asm("{ .reg .u64 t; cvta.to.shared.u64 t, %1; cvt.u32.u64 %0, t; }" : "=r"(a) : "l"(p));
    return a;
}
__device__ __forceinline__ void cp_async16(uint32_t dst, const void* src) {
    asm volatile("cp.async.cg.shared.global [%0], [%1], 16;" :: "r"(dst), "l"(src));
}
__device__ __forceinline__ void cp_commit() {
    asm volatile("cp.async.commit_group;" ::: "memory");
}
__device__ __forceinline__ void cp_wait1() {
    asm volatile("cp.async.wait_group 1;" ::: "memory");
}
__device__ __forceinline__ void cp_wait0() {
    asm volatile("cp.async.wait_group 0;" ::: "memory");
}
__device__ __forceinline__ void ldm_x4(uint32_t* r, uint32_t addr) {
    asm volatile("ldmatrix.sync.aligned.m8n8.x4.shared.b16 {%0,%1,%2,%3}, [%4];"
                 : "=r"(r[0]), "=r"(r[1]), "=r"(r[2]), "=r"(r[3]) : "r"(addr));
}
__device__ __forceinline__ void ldm_x4_t(uint32_t* r, uint32_t addr) {
    asm volatile("ldmatrix.sync.aligned.m8n8.x4.trans.shared.b16 {%0,%1,%2,%3}, [%4];"
                 : "=r"(r[0]), "=r"(r[1]), "=r"(r[2]), "=r"(r[3]) : "r"(addr));
}
__device__ __forceinline__ void mma_bf16(float* c, const uint32_t* a, const uint32_t* b) {
    asm("mma.sync.aligned.m16n8k16.row.col.f32.bf16.bf16.f32 "
        "{%0,%1,%2,%3}, {%4,%5,%6,%7}, {%8,%9}, {%0,%1,%2,%3};"
        : "+f"(c[0]), "+f"(c[1]), "+f"(c[2]), "+f"(c[3])
        : "r"(a[0]), "r"(a[1]), "r"(a[2]), "r"(a[3]), "r"(b[0]), "r"(b[1]));
}
__device__ __forceinline__ uint32_t pack_bf2(__nv_bfloat16 a, __nv_bfloat16 b) {
    __nv_bfloat162 t(a, b);
    return *reinterpret_cast<uint32_t*>(&t);
}
// exp2 polynomial (degree-6, rel err <= ~3e-5), FMA-pipe only
__device__ __forceinline__ float exp2p(float t) {
    t = fmaxf(t, -126.f);
    float fl = floorf(t);
    float f = t - fl;
    float p = 1.5403530e-4f;
    p = fmaf(p, f, 1.3333558e-3f);
    p = fmaf(p, f, 9.6181291e-3f);
    p = fmaf(p, f, 5.5504109e-2f);
    p = fmaf(p, f, 2.4022651e-1f);
    p = fmaf(p, f, 6.9314718e-1f);
    p = fmaf(p, f, 1.0f);
    return p * __int_as_float(((int)fl + 127) << 23);
}

// ---------------------------------------------------------------------------
// fp32 -> split bf16 (hi + lo)
// ---------------------------------------------------------------------------
__global__ void split_bf16_kernel(const float* __restrict__ in,
                                  __nv_bfloat16* __restrict__ hi,
                                  __nv_bfloat16* __restrict__ lo, int n4)
{
    int i = blockIdx.x * blockDim.x + threadIdx.x;
    if (i >= n4) return;
    float4 v = ((const float4*)in)[i];
    __nv_bfloat16 hx = __float2bfloat16(v.x);
    __nv_bfloat16 hy = __float2bfloat16(v.y);
    __nv_bfloat16 hz = __float2bfloat16(v.z);
    __nv_bfloat16 hw = __float2bfloat16(v.w);
    __nv_bfloat16 lx = __float2bfloat16(v.x - __bfloat162float(hx));
    __nv_bfloat16 ly = __float2bfloat16(v.y - __bfloat162float(hy));
    __nv_bfloat16 lz = __float2bfloat16(v.z - __bfloat162float(hz));
    __nv_bfloat16 lw = __float2bfloat16(v.w - __bfloat162float(hw));
    ((__nv_bfloat162*)hi)[2 * i]     = __nv_bfloat162(hx, hy);
    ((__nv_bfloat162*)hi)[2 * i + 1] = __nv_bfloat162(hz, hw);
    ((__nv_bfloat162*)lo)[2 * i]     = __nv_bfloat162(lx, ly);
    ((__nv_bfloat162*)lo)[2 * i + 1] = __nv_bfloat162(lz, lw);
}

// ---------------------------------------------------------------------------
// Split-bf16 mma.sync GEMM: C = A @ B^T + bias.
// 3-stage cp.async ring, __launch_bounds__(256,2) -> 2 CTAs/SM (4 warps/SMSP)
// ---------------------------------------------------------------------------
#define GM_TILE_BYTES 8192
#define GM_STAGE (4 * GM_TILE_BYTES)       // 32 KB per stage
#define GM_NSTAGE 3
#define GM_SMEM (GM_NSTAGE * GM_STAGE)     // 96 KB per CTA

__device__ __forceinline__ void issue_tile(uint32_t smem_tile,
                                           const __nv_bfloat16* __restrict__ G,
                                           int row0, int k0, int K, int tid)
{
#pragma unroll
    for (int t = 0; t < 2; t++) {
        int id = tid + t * 256;
        int r  = id >> 2;
        int c  = id & 3;
        int pc = c ^ ((r >> 1) & 3);
        cp_async16(smem_tile + r * 64 + pc * 16,
                   G + (size_t)(row0 + r) * K + k0 + c * 8);
    }
}
__device__ __forceinline__ void issue_stage(uint32_t base,
                                            const __nv_bfloat16* Ah, const __nv_bfloat16* Al,
                                            const __nv_bfloat16* Bh, const __nv_bfloat16* Bl,
                                            int m0, int n0, int k0, int K, int tid)
{
    issue_tile(base + 0 * GM_TILE_BYTES, Ah, m0, k0, K, tid);
    issue_tile(base + 1 * GM_TILE_BYTES, Al, m0, k0, K, tid);
    issue_tile(base + 2 * GM_TILE_BYTES, Bh, n0, k0, K, tid);
    issue_tile(base + 3 * GM_TILE_BYTES, Bl, n0, k0, K, tid);
}

__global__ __launch_bounds__(256, 2) void gemm_mma(
    const __nv_bfloat16* __restrict__ Ah, const __nv_bfloat16* __restrict__ Al,
    const __nv_bfloat16* __restrict__ Bh, const __nv_bfloat16* __restrict__ Bl,
    const float* __restrict__ bias, float* __restrict__ Cf,
    __nv_bfloat16* __restrict__ Ch, __nv_bfloat16* __restrict__ Cl,
    int M, int N, int K)
{
    extern __shared__ char smc[];
    const uint32_t sb = smem_u32(smc);
    const int tid = threadIdx.x;
    const int lane = tid & 31;
    const int wid = tid >> 5;
    const int wm = wid & 1;
    const int wn = wid >> 1;
    const int m0 = blockIdx.y * 128;
    const int n0 = blockIdx.x * 128;

    const int S = K >> 5;

    // prologue: stages 0, 1
#pragma unroll
    for (int s = 0; s < 2; s++) {
        issue_stage(sb + s * GM_STAGE, Ah, Al, Bh, Bl, m0, n0, s * 32, K, tid);
        cp_commit();
    }

    float acc[4][4][4];
#pragma unroll
    for (int i = 0; i < 4; i++)
#pragma unroll
        for (int j = 0; j < 4; j++)
#pragma unroll
            for (int r = 0; r < 4; r++) acc[i][j][r] = 0.f;

    const int a_r = wm * 64 + (lane & 15);
    const int a_c = (lane >> 4);
    const int b_sub = lane >> 3;
    const int b_r = wn * 32 + (lane & 7) + (b_sub >> 1) * 8;
    const int b_c = (b_sub & 1);

    int buf = 0;
    for (int s = 0; s < S; s++) {
        cp_wait1();                // stage s resident; s+1 in flight
        __syncthreads();           // stage (s+2)%3 buffer free

        if (s + 2 < S) {
            int nb = buf + 2; if (nb >= 3) nb -= 3;
            issue_stage(sb + nb * GM_STAGE, Ah, Al, Bh, Bl,
                        m0, n0, (s + 2) * 32, K, tid);
        }
        cp_commit();               // uniform group counting through drain

        const uint32_t base = sb + buf * GM_STAGE;
        const uint32_t tAh = base;
        const uint32_t tAl = base + GM_TILE_BYTES;
        const uint32_t tBh = base + 2 * GM_TILE_BYTES;
        const uint32_t tBl = base + 3 * GM_TILE_BYTES;

#pragma unroll
        for (int ks = 0; ks < 2; ks++) {
            uint32_t ah[4][4], al[4][4], bh[4][2], bl[4][2];
#pragma unroll
            for (int mt = 0; mt < 4; mt++) {
                int r = a_r + mt * 16;
                int pc = (ks * 2 + a_c) ^ ((r >> 1) & 3);
                uint32_t off = r * 64 + pc * 16;
                ldm_x4(ah[mt], tAh + off);
                ldm_x4(al[mt], tAl + off);
            }
#pragma unroll
            for (int g = 0; g < 2; g++) {
                int r = b_r + g * 16;
                int pc = (ks * 2 + b_c) ^ ((r >> 1) & 3);
                uint32_t off = r * 64 + pc * 16;
                uint32_t th[4], tl[4];
                ldm_x4(th, tBh + off);
                ldm_x4(tl, tBl + off);
                bh[g * 2][0] = th[0]; bh[g * 2][1] = th[1];
                bh[g * 2 + 1][0] = th[2]; bh[g * 2 + 1][1] = th[3];
                bl[g * 2][0] = tl[0]; bl[g * 2][1] = tl[1];
                bl[g * 2 + 1][0] = tl[2]; bl[g * 2 + 1][1] = tl[3];
            }
#pragma unroll
            for (int mt = 0; mt < 4; mt++)
#pragma unroll
                for (int nt = 0; nt < 4; nt++)
                    mma_bf16(acc[mt][nt], ah[mt], bh[nt]);
#pragma unroll
            for (int mt = 0; mt < 4; mt++)
#pragma unroll
                for (int nt = 0; nt < 4; nt++)
                    mma_bf16(acc[mt][nt], al[mt], bh[nt]);
#pragma unroll
            for (int mt = 0; mt < 4; mt++)
#pragma unroll
                for (int nt = 0; nt < 4; nt++)
                    mma_bf16(acc[mt][nt], ah[mt], bl[nt]);
        }
        buf++; if (buf >= 3) buf = 0;
    }

    const int cm = m0 + wm * 64 + (lane >> 2);
    const int cn = n0 + wn * 32 + (lane & 3) * 2;
    if (Cf) {
#pragma unroll
        for (int nt = 0; nt < 4; nt++) {
            float b0 = bias[cn + nt * 8];
            float b1 = bias[cn + nt * 8 + 1];
#pragma unroll
            for (int mt = 0; mt < 4; mt++) {
                float* r0 = Cf + (size_t)(cm + mt * 16) * N + cn + nt * 8;
                float* r1 = r0 + 8 * N;
                *(float2*)r0 = make_float2(acc[mt][nt][0] + b0, acc[mt][nt][1] + b1);
                *(float2*)r1 = make_float2(acc[mt][nt][2] + b0, acc[mt][nt][3] + b1);
            }
        }
    } else {
#pragma unroll
        for (int nt = 0; nt < 4; nt++) {
            float b0 = bias[cn + nt * 8];
            float b1 = bias[cn + nt * 8 + 1];
#pragma unroll
            for (int mt = 0; mt < 4; mt++) {
#pragma unroll
                for (int half = 0; half < 2; half++) {
                    float v0 = acc[mt][nt][2 * half + 0] + b0;
                    float v1 = acc[mt][nt][2 * half + 1] + b1;
                    __nv_bfloat16 h0 = __float2bfloat16(v0);
                    __nv_bfloat16 h1 = __float2bfloat16(v1);
                    __nv_bfloat16 l0 = __float2bfloat16(v0 - __bfloat162float(h0));
                    __nv_bfloat16 l1 = __float2bfloat16(v1 - __bfloat162float(h1));
                    size_t off = (size_t)(cm + mt * 16 + half * 8) * N + cn + nt * 8;
                    *(uint32_t*)(Ch + off) = pack_bf2(h0, h1);
                    *(uint32_t*)(Cl + off) = pack_bf2(l0, l1);
                }
            }
        }
    }
}

// ---------------------------------------------------------------------------
// Tensor-core flash attention (unchanged from R6 passing kernel)
// ---------------------------------------------------------------------------
#define ATT_STAGE 65536
#define ATT_SMEM (2 * ATT_STAGE)
#define ATT_NT 32

__device__ __forceinline__ uint32_t sw_addr(uint32_t base, int r, int c) {
    return base + r * 256 + ((c ^ (r & 7)) << 4);
}
__device__ __forceinline__ void att_load_tile(uint32_t dst,
                                              const __nv_bfloat16* __restrict__ g,
                                              int k0, int tid)
{
#pragma unroll
    for (int i = 0; i < 4; i++) {
        int id = tid + i * 256;
        int r = id >> 4;
        int c = id & 15;
        cp_async16(sw_addr(dst, r, c), g + (size_t)(k0 + r) * E3 + c * 8);
    }
}

__global__ __launch_bounds__(256, 1) void attn_tc(
    const __nv_bfloat16* __restrict__ qkvh, const __nv_bfloat16* __restrict__ qkvl,
    const float* __restrict__ biasM,
    __nv_bfloat16* __restrict__ ch, __nv_bfloat16* __restrict__ cl)
{
    extern __shared__ char smc[];
    const uint32_t sb = smem_u32(smc);
    const int tid = threadIdx.x;
    const int lane = tid & 31;
    const int wid = tid >> 5;
    const int h = blockIdx.y;
    const int q0 = blockIdx.x * 128;

    const uint32_t buf0 = sb;
    const uint32_t buf1 = sb + ATT_STAGE;

    const __nv_bfloat16* gKh = qkvh + E_DIM + h * D_HEAD;
    const __nv_bfloat16* gKl = qkvl + E_DIM + h * D_HEAD;
    const __nv_bfloat16* gVh = qkvh + 2 * E_DIM + h * D_HEAD;
    const __nv_bfloat16* gVl = qkvl + 2 * E_DIM + h * D_HEAD;

    {
        const __nv_bfloat16* gqh = qkvh + (size_t)q0 * E3 + h * D_HEAD;
        const __nv_bfloat16* gql = qkvl + (size_t)q0 * E3 + h * D_HEAD;
#pragma unroll
        for (int i = 0; i < 8; i++) {
            int id = tid + i * 256;
            int r = id >> 4;
            int c = id & 15;
            cp_async16(sw_addr(buf0, r, c), gqh + (size_t)r * E3 + c * 8);
        }
#pragma unroll
        for (int i = 0; i < 8; i++) {
            int id = tid + i * 256;
            int r = id >> 4;
            int c = id & 15;
            cp_async16(sw_addr(buf0 + 32768, r, c), gql + (size_t)r * E3 + c * 8);
        }
        cp_commit();
    }
    att_load_tile(buf1 + 0,     gKh, 0, tid);
    att_load_tile(buf1 + 16384, gKl, 0, tid);
    att_load_tile(buf1 + 32768, gVh, 0, tid);
    att_load_tile(buf1 + 49152, gVl, 0, tid);
    cp_commit();

    cp_wait1();
    __syncthreads();

    uint32_t qh_f[8][4], ql_f[8][4];
    {
        int r = wid * 16 + (lane & 15);
#pragma unroll
        for (int kf = 0; kf < 8; kf++) {
            int c = 2 * kf + (lane >> 4);
            ldm_x4(qh_f[kf], sw_addr(buf0, r, c));
            ldm_x4(ql_f[kf], sw_addr(buf0 + 32768, r, c));
        }
    }
    __syncthreads();

    att_load_tile(buf0 + 0,     gKh, 64, tid);
    att_load_tile(buf0 + 16384, gKl, 64, tid);
    att_load_tile(buf0 + 32768, gVh, 64, tid);
    att_load_tile(buf0 + 49152, gVl, 64, tid);
    cp_commit();

    float mA = -INFINITY, mB = -INFINITY, lA = 0.f, lB = 0.f;
    float ctx[16][4];
#pragma unroll
    for (int i = 0; i < 16; i++)
#pragma unroll
        for (int j = 0; j < 4; j++) ctx[i][j] = 0.f;

    const float SCALE = 0.088388347648318447f;
    const float LOG2E = 1.4426950408889634f;
    const int rA = q0 + wid * 16 + (lane >> 2);
    const int rB = rA + 8;
    const int cb = 2 * (lane & 3);

    const int s_br = (lane & 7) + ((lane >> 4) & 1) * 8;
    const int s_bc = (lane >> 3) & 1;
    const int a_r = (lane & 15);
    const int a_c = (lane >> 4);

    for (int kt = 0; kt < ATT_NT; kt++) {
        if (kt < ATT_NT - 2) cp_wait1(); else cp_wait0();
        __syncthreads();
        const uint32_t buf = (kt & 1) ? buf0 : buf1;
        const int k0 = kt * 64;

        float sacc[8][4];
#pragma unroll
        for (int i = 0; i < 8; i++)
#pragma unroll
            for (int j = 0; j < 4; j++) sacc[i][j] = 0.f;

#pragma unroll
        for (int kf = 0; kf < 8; kf++) {
#pragma unroll
            for (int ng = 0; ng < 4; ng++) {
                int r = ng * 16 + s_br;
                int c = 2 * kf + s_bc;
                uint32_t th[4], tl[4];
                ldm_x4(th, sw_addr(buf + 0, r, c));
                ldm_x4(tl, sw_addr(buf + 16384, r, c));
                uint32_t bh0[2] = {th[0], th[1]}, bh1[2] = {th[2], th[3]};
                uint32_t bl0[2] = {tl[0], tl[1]}, bl1[2] = {tl[2], tl[3]};
                mma_bf16(sacc[2 * ng],     qh_f[kf], bh0);
                mma_bf16(sacc[2 * ng + 1], qh_f[kf], bh1);
                mma_bf16(sacc[2 * ng],     ql_f[kf], bh0);
                mma_bf16(sacc[2 * ng + 1], ql_f[kf], bh1);
                mma_bf16(sacc[2 * ng],     qh_f[kf], bl0);
                mma_bf16(sacc[2 * ng + 1], qh_f[kf], bl1);
            }
        }

        float mxA = -INFINITY, mxB = -INFINITY;
#pragma unroll
        for (int nt = 0; nt < 8; nt++) {
            float2 bA = *(const float2*)(biasM + (size_t)rA * L_SEQ + k0 + nt * 8 + cb);
            float2 bB = *(const float2*)(biasM + (size_t)rB * L_SEQ + k0 + nt * 8 + cb);
            sacc[nt][0] = fmaf(sacc[nt][0], SCALE, bA.x);
            sacc[nt][1] = fmaf(sacc[nt][1], SCALE, bA.y);
            sacc[nt][2] = fmaf(sacc[nt][2], SCALE, bB.x);
            sacc[nt][3] = fmaf(sacc[nt][3], SCALE, bB.y);
            mxA = fmaxf(mxA, fmaxf(sacc[nt][0], sacc[nt][1]));
            mxB = fmaxf(mxB, fmaxf(sacc[nt][2], sacc[nt][3]));
        }
        mxA = fmaxf(mxA, __shfl_xor_sync(0xffffffffu, mxA, 1));
        mxA = fmaxf(mxA, __shfl_xor_sync(0xffffffffu, mxA, 2));
        mxB = fmaxf(mxB, __shfl_xor_sync(0xffffffffu, mxB, 1));
        mxB = fmaxf(mxB, __shfl_xor_sync(0xffffffffu, mxB, 2));
        float mnA = fmaxf(mA, mxA), mnB = fmaxf(mB, mxB);
        float alA = exp2p((mA - mnA) * LOG2E);
        float alB = exp2p((mB - mnB) * LOG2E);
        float negA = mnA * LOG2E, negB = mnB * LOG2E;
        float sumA = 0.f, sumB = 0.f;
#pragma unroll
        for (int nt = 0; nt < 8; nt++) {
            sacc[nt][0] = exp2p(fmaf(sacc[nt][0], LOG2E, -negA));
            sacc[nt][1] = exp2p(fmaf(sacc[nt][1], LOG2E, -negA));
            sacc[nt][2] = exp2p(fmaf(sacc[nt][2], LOG2E, -negB));
            sacc[nt][3] = exp2p(fmaf(sacc[nt][3], LOG2E, -negB));
            sumA += sacc[nt][0] + sacc[nt][1];
            sumB += sacc[nt][2] + sacc[nt][3];
        }
        sumA += __shfl_xor_sync(0xffffffffu, sumA, 1);
        sumA += __shfl_xor_sync(0xffffffffu, sumA, 2);
        sumB += __shfl_xor_sync(0xffffffffu, sumB, 1);
        sumB += __shfl_xor_sync(0xffffffffu, sumB, 2);
        lA = lA * alA + sumA;
        lB = lB * alB + sumB;
        mA = mnA; mB = mnB;
#pragma unroll
        for (int nt = 0; nt < 16; nt++) {
            ctx[nt][0] *= alA; ctx[nt][1] *= alA;
            ctx[nt][2] *= alB; ctx[nt][3] *= alB;
        }

        uint32_t pah[4][4], pal[4][4];
#pragma unroll
        for (int kb = 0; kb < 4; kb++) {
#pragma unroll
            for (int half = 0; half < 2; half++) {
#pragma unroll
                for (int sub = 0; sub < 2; sub++) {
                    float p0 = sacc[2 * kb + sub][2 * half + 0];
                    float p1 = sacc[2 * kb + sub][2 * half + 1];
                    __nv_bfloat16 h0 = __float2bfloat16(p0);
                    __nv_bfloat16 h1 = __float2bfloat16(p1);
                    __nv_bfloat16 l0 = __float2bfloat16(p0 - __bfloat162float(h0));
                    __nv_bfloat16 l1 = __float2bfloat16(p1 - __bfloat162float(h1));
                    pah[kb][sub * 2 + half] = pack_bf2(h0, h1);
                    pal[kb][sub * 2 + half] = pack_bf2(l0, l1);
                }
            }
        }

#pragma unroll
        for (int kb = 0; kb < 4; kb++) {
#pragma unroll
            for (int db = 0; db < 8; db++) {
                int r = kb * 16 + a_r;
                int c = 2 * db + a_c;
                uint32_t th[4], tl[4];
                ldm_x4_t(th, sw_addr(buf + 32768, r, c));
                ldm_x4_t(tl, sw_addr(buf + 49152, r, c));
                uint32_t bh0[2] = {th[0], th[1]}, bh1[2] = {th[2], th[3]};
                uint32_t bl0[2] = {tl[0], tl[1]}, bl1[2] = {tl[2], tl[3]};
                mma_bf16(ctx[2 * db],     pah[kb], bh0);
                mma_bf16(ctx[2 * db + 1], pah[kb], bh1);
                mma_bf16(ctx[2 * db],     pal[kb], bh0);
                mma_bf16(ctx[2 * db + 1], pal[kb], bh1);
                mma_bf16(ctx[2 * db],     pah[kb], bl0);
                mma_bf16(ctx[2 * db + 1], pah[kb], bl1);
            }
        }

        __syncthreads();
        if (kt + 2 < ATT_NT) {
            const uint32_t nbuf = (kt & 1) ? buf0 : buf1;
            const int nk0 = (kt + 2) * 64;
            att_load_tile(nbuf + 0,     gKh, nk0, tid);
            att_load_tile(nbuf + 16384, gKl, nk0, tid);
            att_load_tile(nbuf + 32768, gVh, nk0, tid);
            att_load_tile(nbuf + 49152, gVl, nk0, tid);
            cp_commit();
        }
    }

    float iA = 1.f / lA, iB = 1.f / lB;
#pragma unroll
    for (int nt = 0; nt < 16; nt++) {
        int col = h * D_HEAD + nt * 8 + cb;
        float v0 = ctx[nt][0] * iA, v1 = ctx[nt][1] * iA;
        float v2 = ctx[nt][2] * iB, v3 = ctx[nt][3] * iB;
        __nv_bfloat16 h0 = __float2bfloat16(v0), h1 = __float2bfloat16(v1);
        __nv_bfloat16 h2 = __float2bfloat16(v2), h3 = __float2bfloat16(v3);
        __nv_bfloat16 l0 = __float2bfloat16(v0 - __bfloat162float(h0));
        __nv_bfloat16 l1 = __float2bfloat16(v1 - __bfloat162float(h1));
        __nv_bfloat16 l2 = __float2bfloat16(v2 - __bfloat162float(h2));
        __nv_bfloat16 l3 = __float2bfloat16(v3 - __bfloat162float(h3));
        *(uint32_t*)(ch + (size_t)rA * E_DIM + col) = pack_bf2(h0, h1);
        *(uint32_t*)(cl + (size_t)rA * E_DIM + col) = pack_bf2(l0, l1);
        *(uint32_t*)(ch + (size_t)rB * E_DIM + col) = pack_bf2(h2, h3);
        *(uint32_t*)(cl + (size_t)rB * E_DIM + col) = pack_bf2(l2, l3);
    }
}

// ---------------------------------------------------------------------------
extern "C" void kernel_launch(void* const* d_in, const int* in_sizes, int n_in,
                              void* d_out, int out_size)
{
    const float* x     = (const float*)d_in[0];
    const float* biasM = (const float*)d_in[1];
    const float* w_in  = (const float*)d_in[2];
    const float* b_in  = (const float*)d_in[3];
    const float* w_out = (const float*)d_in[4];
    const float* b_out = (const float*)d_in[5];
    float* out = (float*)d_out;

    __nv_bfloat16 *xh, *xl, *wih, *wil, *woh, *wol, *qkvh, *qkvl, *ch, *cl;
    cudaGetSymbolAddress((void**)&xh, g_xh);
    cudaGetSymbolAddress((void**)&xl, g_xl);
    cudaGetSymbolAddress((void**)&wih, g_wih);
    cudaGetSymbolAddress((void**)&wil, g_wil);
    cudaGetSymbolAddress((void**)&woh, g_woh);
    cudaGetSymbolAddress((void**)&wol, g_wol);
    cudaGetSymbolAddress((void**)&qkvh, g_qkvh);
    cudaGetSymbolAddress((void**)&qkvl, g_qkvl);
    cudaGetSymbolAddress((void**)&ch, g_ch);
    cudaGetSymbolAddress((void**)&cl, g_cl);

    cudaFuncSetAttribute(gemm_mma, cudaFuncAttributeMaxDynamicSharedMemorySize, GM_SMEM);
    cudaFuncSetAttribute(attn_tc, cudaFuncAttributeMaxDynamicSharedMemorySize, ATT_SMEM);

    {
        int n4 = (L_SEQ * E_DIM) / 4;
        split_bf16_kernel<<<(n4 + 255) / 256, 256>>>(x, xh, xl, n4);
        int w4 = (E3 * E_DIM) / 4;
        split_bf16_kernel<<<(w4 + 255) / 256, 256>>>(w_in, wih, wil, w4);
        int o4 = (E_DIM * E_DIM) / 4;
        split_bf16_kernel<<<(o4 + 255) / 256, 256>>>(w_out, woh, wol, o4);
    }

    // 1) QKV projection -> split bf16 output
    gemm_mma<<<dim3(E3 / 128, L_SEQ / 128), 256, GM_SMEM>>>(
        xh, xl, wih, wil, b_in, nullptr, qkvh, qkvl, L_SEQ, E3, E_DIM);

    // 2) Tensor-core attention -> split bf16 ctx
    attn_tc<<<dim3(L_SEQ / 128, H_NUM), 256, ATT_SMEM>>>(
        qkvh, qkvl, biasM, ch, cl);

    // 3) out projection -> fp32 output
    gemm_mma<<<dim3(E_DIM / 128, L_SEQ / 128), 256, GM_SMEM>>>(
        ch, cl, woh, wol, b_out, out, nullptr, nullptr, L_SEQ, E_DIM, E_DIM);
}